// round 1
// baseline (speedup 1.0000x reference)
#include <cuda_runtime.h>

#define Bsz 16384
#define Dd 512
#define Hh 256
#define Rr 95

// Scratch (allocation-free rule: __device__ globals)
__device__ float g_act[2][Bsz][Hh];   // post-GELU activations
__device__ float g_m[2][Bsz][64];     // mp / mv multivectors (flattened K*8)

__device__ __forceinline__ float gelu_exact(float x) {
    return 0.5f * x * (1.0f + erff(x * 0.70710678118654752440f));
}

// Reorder sign for blade product e_a * e_b (3-bit masks), Cl(3,0)
__device__ __forceinline__ float csign(int a, int b) {
    int sw = __popc((a >> 1) & b) + __popc((a >> 2) & b);
    return (sw & 1) ? -1.0f : 1.0f;
}
// mask -> component index in order [1,e1,e2,e3,e12,e13,e23,e123] (swap 3<->4)
__device__ __forceinline__ int cidx(int m) { return m + (m == 3) - (m == 4); }

// ---------------------------------------------------------------------------
// K1: X(B,512) @ W1(512,256) + b1 -> LayerNorm -> GELU -> g_act[which]
// BM=64, BN=256 (full H), BK=32. 256 threads, thread tile 4 rows x 16 cols.
// ---------------------------------------------------------------------------
__global__ __launch_bounds__(256) void k1_proj1(
    const float* __restrict__ Xp, const float* __restrict__ Xv,
    const float* __restrict__ W1p, const float* __restrict__ W1v,
    const float* __restrict__ b1p, const float* __restrict__ b1v,
    const float* __restrict__ lgp, const float* __restrict__ lgv,
    const float* __restrict__ lbp, const float* __restrict__ lbv)
{
    const int which = blockIdx.y;
    const float* __restrict__ X  = which ? Xv  : Xp;
    const float* __restrict__ W1 = which ? W1v : W1p;
    const float* __restrict__ b1 = which ? b1v : b1p;
    const float* __restrict__ lg = which ? lgv : lgp;
    const float* __restrict__ lb = which ? lbv : lbp;

    __shared__ float Xs[32][68];    // [k][row], padded (68*4B = 17*16B aligned)
    __shared__ float Ws[32][256];   // [k][col]

    const int tid = threadIdx.x;
    const int tx = tid & 15;        // col group: cols tx*16 .. tx*16+15
    const int ty = tid >> 4;        // row group: rows ty*4 .. ty*4+3
    const int row0 = blockIdx.x * 64;

    float acc[4][16];
    #pragma unroll
    for (int i = 0; i < 4; i++)
        #pragma unroll
        for (int j = 0; j < 16; j++) acc[i][j] = 0.0f;

    float4 xr[2], wr[8];
    // prefetch tile 0
    #pragma unroll
    for (int q = 0; q < 2; q++) {
        int idx = tid + q * 256;
        xr[q] = *reinterpret_cast<const float4*>(&X[(row0 + (idx >> 3)) * Dd + (idx & 7) * 4]);
    }
    #pragma unroll
    for (int q = 0; q < 8; q++) {
        int idx = tid + q * 256;
        wr[q] = *reinterpret_cast<const float4*>(&W1[(idx >> 6) * Hh + (idx & 63) * 4]);
    }

    #pragma unroll 1
    for (int kt = 0; kt < 16; kt++) {
        __syncthreads();
        #pragma unroll
        for (int q = 0; q < 2; q++) {
            int idx = tid + q * 256;
            int r = idx >> 3, c4 = (idx & 7) * 4;
            Xs[c4 + 0][r] = xr[q].x; Xs[c4 + 1][r] = xr[q].y;
            Xs[c4 + 2][r] = xr[q].z; Xs[c4 + 3][r] = xr[q].w;
        }
        #pragma unroll
        for (int q = 0; q < 8; q++) {
            int idx = tid + q * 256;
            *reinterpret_cast<float4*>(&Ws[idx >> 6][(idx & 63) * 4]) = wr[q];
        }
        __syncthreads();

        if (kt < 15) {
            int kn = (kt + 1) * 32;
            #pragma unroll
            for (int q = 0; q < 2; q++) {
                int idx = tid + q * 256;
                xr[q] = *reinterpret_cast<const float4*>(&X[(row0 + (idx >> 3)) * Dd + kn + (idx & 7) * 4]);
            }
            #pragma unroll
            for (int q = 0; q < 8; q++) {
                int idx = tid + q * 256;
                wr[q] = *reinterpret_cast<const float4*>(&W1[(kn + (idx >> 6)) * Hh + (idx & 63) * 4]);
            }
        }

        #pragma unroll 8
        for (int kk = 0; kk < 32; kk++) {
            float4 a = *reinterpret_cast<const float4*>(&Xs[kk][ty * 4]);
            float av[4] = {a.x, a.y, a.z, a.w};
            float wv[16];
            #pragma unroll
            for (int j4 = 0; j4 < 4; j4++) {
                float4 wq = *reinterpret_cast<const float4*>(&Ws[kk][tx * 16 + j4 * 4]);
                wv[j4 * 4 + 0] = wq.x; wv[j4 * 4 + 1] = wq.y;
                wv[j4 * 4 + 2] = wq.z; wv[j4 * 4 + 3] = wq.w;
            }
            #pragma unroll
            for (int i = 0; i < 4; i++)
                #pragma unroll
                for (int j = 0; j < 16; j++)
                    acc[i][j] = fmaf(av[i], wv[j], acc[i][j]);
        }
    }

    // Epilogue: bias + LayerNorm (per-row over 256, row = 16 lanes) + GELU
    const int c0 = tx * 16;
    float bcol[16], lgc[16], lbc[16];
    #pragma unroll
    for (int j = 0; j < 16; j++) {
        bcol[j] = __ldg(&b1[c0 + j]);
        lgc[j]  = __ldg(&lg[c0 + j]);
        lbc[j]  = __ldg(&lb[c0 + j]);
    }

    #pragma unroll
    for (int i = 0; i < 4; i++) {
        float s = 0.0f, s2 = 0.0f;
        #pragma unroll
        for (int j = 0; j < 16; j++) {
            float v = acc[i][j] + bcol[j];
            acc[i][j] = v;
            s += v; s2 += v * v;
        }
        #pragma unroll
        for (int o = 1; o < 16; o <<= 1) {
            s  += __shfl_xor_sync(0xffffffffu, s,  o);
            s2 += __shfl_xor_sync(0xffffffffu, s2, o);
        }
        float mu   = s * (1.0f / 256.0f);
        float var  = s2 * (1.0f / 256.0f) - mu * mu;
        float rstd = rsqrtf(var + 1e-5f);
        int row = row0 + ty * 4 + i;
        #pragma unroll
        for (int j4 = 0; j4 < 4; j4++) {
            float4 ov;
            float v0 = (acc[i][j4*4+0] - mu) * rstd * lgc[j4*4+0] + lbc[j4*4+0];
            float v1 = (acc[i][j4*4+1] - mu) * rstd * lgc[j4*4+1] + lbc[j4*4+1];
            float v2 = (acc[i][j4*4+2] - mu) * rstd * lgc[j4*4+2] + lbc[j4*4+2];
            float v3 = (acc[i][j4*4+3] - mu) * rstd * lgc[j4*4+3] + lbc[j4*4+3];
            ov.x = gelu_exact(v0); ov.y = gelu_exact(v1);
            ov.z = gelu_exact(v2); ov.w = gelu_exact(v3);
            *reinterpret_cast<float4*>(&g_act[which][row][c0 + j4 * 4]) = ov;
        }
    }
}

// ---------------------------------------------------------------------------
// K2: g_act(B,256) @ W2(256,64) + b2 -> g_m[which]
// BM=128, BN=64, BK=32. 256 threads, thread tile 8 rows x 4 cols.
// ---------------------------------------------------------------------------
__global__ __launch_bounds__(256) void k2_proj2(
    const float* __restrict__ W2p, const float* __restrict__ W2v,
    const float* __restrict__ b2p, const float* __restrict__ b2v)
{
    const int which = blockIdx.y;
    const float* __restrict__ W2 = which ? W2v : W2p;
    const float* __restrict__ b2 = which ? b2v : b2p;
    const float* __restrict__ A  = &g_act[which][0][0];

    __shared__ float As[32][132];   // [k][row], 132*4B = 33*16B aligned
    __shared__ float Ws2[32][64];   // [k][col]

    const int tid = threadIdx.x;
    const int tx = tid & 15;        // col = tx*4
    const int ty = tid >> 4;        // rows = ty*8 .. ty*8+7
    const int row0 = blockIdx.x * 128;

    float acc[8][4];
    #pragma unroll
    for (int i = 0; i < 8; i++)
        #pragma unroll
        for (int j = 0; j < 4; j++) acc[i][j] = 0.0f;

    float4 ar[4], wr2[2];
    #pragma unroll
    for (int q = 0; q < 4; q++) {
        int idx = tid + q * 256;
        ar[q] = *reinterpret_cast<const float4*>(&A[(row0 + (idx >> 3)) * Hh + (idx & 7) * 4]);
    }
    #pragma unroll
    for (int q = 0; q < 2; q++) {
        int idx = tid + q * 256;
        wr2[q] = *reinterpret_cast<const float4*>(&W2[(idx >> 4) * 64 + (idx & 15) * 4]);
    }

    #pragma unroll 1
    for (int kt = 0; kt < 8; kt++) {
        __syncthreads();
        #pragma unroll
        for (int q = 0; q < 4; q++) {
            int idx = tid + q * 256;
            int r = idx >> 3, c4 = (idx & 7) * 4;
            As[c4 + 0][r] = ar[q].x; As[c4 + 1][r] = ar[q].y;
            As[c4 + 2][r] = ar[q].z; As[c4 + 3][r] = ar[q].w;
        }
        #pragma unroll
        for (int q = 0; q < 2; q++) {
            int idx = tid + q * 256;
            *reinterpret_cast<float4*>(&Ws2[idx >> 4][(idx & 15) * 4]) = wr2[q];
        }
        __syncthreads();

        if (kt < 7) {
            int kn = (kt + 1) * 32;
            #pragma unroll
            for (int q = 0; q < 4; q++) {
                int idx = tid + q * 256;
                ar[q] = *reinterpret_cast<const float4*>(&A[(row0 + (idx >> 3)) * Hh + kn + (idx & 7) * 4]);
            }
            #pragma unroll
            for (int q = 0; q < 2; q++) {
                int idx = tid + q * 256;
                wr2[q] = *reinterpret_cast<const float4*>(&W2[(kn + (idx >> 4)) * 64 + (idx & 15) * 4]);
            }
        }

        #pragma unroll 8
        for (int kk = 0; kk < 32; kk++) {
            float4 alo = *reinterpret_cast<const float4*>(&As[kk][ty * 8]);
            float4 ahi = *reinterpret_cast<const float4*>(&As[kk][ty * 8 + 4]);
            float4 w   = *reinterpret_cast<const float4*>(&Ws2[kk][tx * 4]);
            float av[8] = {alo.x, alo.y, alo.z, alo.w, ahi.x, ahi.y, ahi.z, ahi.w};
            float wv[4] = {w.x, w.y, w.z, w.w};
            #pragma unroll
            for (int i = 0; i < 8; i++)
                #pragma unroll
                for (int j = 0; j < 4; j++)
                    acc[i][j] = fmaf(av[i], wv[j], acc[i][j]);
        }
    }

    float4 bc = *reinterpret_cast<const float4*>(&b2[tx * 4]);
    #pragma unroll
    for (int i = 0; i < 8; i++) {
        int row = row0 + ty * 8 + i;
        float4 ov;
        ov.x = acc[i][0] + bc.x; ov.y = acc[i][1] + bc.y;
        ov.z = acc[i][2] + bc.z; ov.w = acc[i][3] + bc.w;
        *reinterpret_cast<float4*>(&g_m[which][row][tx * 4]) = ov;
    }
}

// ---------------------------------------------------------------------------
// K3: Clifford triple-product collapse + readout GEMM vs T.
// weighted[b,r,k] = sum_j T[r,k,j] * Q[b,k,j]
//   V[k][u]  = sum_jm mv[k,jm] * sign(u, m_jm) * gw[idx(u ^ m_jm)]
//   Q[k,jc]  = sum_i  mp[k,i]  * sign(m_i, m_jc) * V[k][m_i ^ m_jc]
// out[b,r] = (1/8) * sum_f T[r,f] * Q[b,f]
// One warp per batch row; 8 warps / block.
// ---------------------------------------------------------------------------
__global__ __launch_bounds__(256) void k3_triple(
    const float* __restrict__ T, const float* __restrict__ gw,
    float* __restrict__ out)
{
    __shared__ float Ts[Rr * 65];      // padded stride 65: conflict-free
    __shared__ float s_gw[8];
    __shared__ float s_mp[8][64], s_mv[8][64], s_V[8][64], s_Q[8][64];

    const int tid = threadIdx.x;
    const int lane = tid & 31;
    const int w = tid >> 5;

    for (int i = tid; i < Rr * 64; i += 256)
        Ts[(i >> 6) * 65 + (i & 63)] = T[i];
    if (tid < 8) s_gw[tid] = gw[tid];
    __syncthreads();

    const int row = blockIdx.x * 8 + w;

    s_mp[w][lane]      = g_m[0][row][lane];
    s_mp[w][lane + 32] = g_m[0][row][lane + 32];
    s_mv[w][lane]      = g_m[1][row][lane];
    s_mv[w][lane + 32] = g_m[1][row][lane + 32];
    __syncwarp();

    const int MASKS_[8] = {0, 1, 2, 4, 3, 5, 6, 7};

    // V stage: index u is the raw 3-bit mask
    #pragma unroll
    for (int h = 0; h < 2; h++) {
        int f = lane + h * 32;
        int k = f >> 3, u = f & 7;
        float v = 0.0f;
        #pragma unroll
        for (int jm = 0; jm < 8; jm++) {
            int mj = MASKS_[jm];
            v += s_mv[w][k * 8 + jm] * csign(u, mj) * s_gw[cidx(u ^ mj)];
        }
        s_V[w][f] = v;
    }
    __syncwarp();

    // Q stage
    #pragma unroll
    for (int h = 0; h < 2; h++) {
        int f = lane + h * 32;
        int k = f >> 3, jc = f & 7;
        int mjc = MASKS_[jc];
        float q = 0.0f;
        #pragma unroll
        for (int i = 0; i < 8; i++) {
            int mi = MASKS_[i];
            q += s_mp[w][k * 8 + i] * csign(mi, mjc) * s_V[w][k * 8 + (mi ^ mjc)];
        }
        s_Q[w][f] = q;
    }
    __syncwarp();

    // readout: out[row, r] = (1/8) * sum_f Ts[r][f] * Q[f]
    #pragma unroll
    for (int h = 0; h < 3; h++) {
        int r = lane + h * 32;
        if (r < Rr) {
            float a = 0.0f;
            #pragma unroll
            for (int f = 0; f < 64; f++)
                a = fmaf(Ts[r * 65 + f], s_Q[w][f], a);
            out[row * Rr + r] = a * 0.125f;
        }
    }
}

// ---------------------------------------------------------------------------
extern "C" void kernel_launch(void* const* d_in, const int* in_sizes, int n_in,
                              void* d_out, int out_size)
{
    const float* h_perp = (const float*)d_in[0];
    const float* h_vuln = (const float*)d_in[1];
    const float* Wp1    = (const float*)d_in[2];
    const float* bp1    = (const float*)d_in[3];
    const float* lgp    = (const float*)d_in[4];
    const float* lbp    = (const float*)d_in[5];
    const float* Wp2    = (const float*)d_in[6];
    const float* bp2    = (const float*)d_in[7];
    const float* Wv1    = (const float*)d_in[8];
    const float* bv1    = (const float*)d_in[9];
    const float* lgv    = (const float*)d_in[10];
    const float* lbv    = (const float*)d_in[11];
    const float* Wv2    = (const float*)d_in[12];
    const float* bv2    = (const float*)d_in[13];
    const float* T      = (const float*)d_in[14];
    const float* gw     = (const float*)d_in[15];
    float* out = (float*)d_out;

    dim3 g1(Bsz / 64, 2);
    k1_proj1<<<g1, 256>>>(h_perp, h_vuln, Wp1, Wv1, bp1, bv1, lgp, lgv, lbp, lbv);
    dim3 g2(Bsz / 128, 2);
    k2_proj2<<<g2, 256>>>(Wp2, Wv2, bp2, bv2);
    k3_triple<<<Bsz / 8, 256>>>(T, gw, out);
}

// round 2
// speedup vs baseline: 2.4485x; 2.4485x over previous
#include <cuda_runtime.h>
#include <stdint.h>

#define Bsz 16384
#define Dd 512
#define Hh 256
#define Rr 95

// Scratch (__device__ globals: allocation-free rule)
__device__ float g_pre[2][Bsz][Hh];   // pre-LN GEMM1 output
__device__ float g_act[2][Bsz][Hh];   // post-GELU activations
__device__ float g_m[2][Bsz][64];     // mp / mv multivectors

__device__ __forceinline__ float gelu_exact(float x) {
    return 0.5f * x * (1.0f + erff(x * 0.70710678118654752440f));
}
__device__ __forceinline__ float csign(int a, int b) {
    int sw = __popc((a >> 1) & b) + __popc((a >> 2) & b);
    return (sw & 1) ? -1.0f : 1.0f;
}
__device__ __forceinline__ int cidx(int m) { return m + (m == 3) - (m == 4); }

// tf32 hi/lo split (3xTF32 trick, cutlass-style)
__device__ __forceinline__ void tf32_split(float x, uint32_t& hi, uint32_t& lo) {
    asm("cvt.rna.tf32.f32 %0, %1;" : "=r"(hi) : "f"(x));
    float r = x - __uint_as_float(hi);
    asm("cvt.rna.tf32.f32 %0, %1;" : "=r"(lo) : "f"(r));
}

#define MMA_TF32(d, a, b) \
    asm volatile("mma.sync.aligned.m16n8k8.row.col.f32.tf32.tf32.f32 " \
        "{%0,%1,%2,%3}, {%4,%5,%6,%7}, {%8,%9}, {%0,%1,%2,%3};" \
        : "+f"(d[0]), "+f"(d[1]), "+f"(d[2]), "+f"(d[3]) \
        : "r"(a[0]), "r"(a[1]), "r"(a[2]), "r"(a[3]), "r"(b[0]), "r"(b[1]))

// ---------------------------------------------------------------------------
// GEMM1: Y(B,256) = X(B,512) @ W1(512,256), tf32 3x.
// BM=128, BN=128, BK=16. 256 thr, 8 warps (2m x 4n), warp tile 64x32.
// grid: (M/128, N/128=2, side=2)
// ---------------------------------------------------------------------------
__global__ __launch_bounds__(256) void k_gemm1(
    const float* __restrict__ Xp, const float* __restrict__ Xv,
    const float* __restrict__ W1p, const float* __restrict__ W1v)
{
    const int side = blockIdx.z;
    const float* __restrict__ X = side ? Xv : Xp;
    const float* __restrict__ W = side ? W1v : W1p;

    __shared__ uint32_t Ah[16][136], Al[16][136], Bh[16][136], Bl[16][136];

    const int tid  = threadIdx.x;
    const int lane = tid & 31;
    const int wid  = tid >> 5;
    const int gid  = lane >> 2;
    const int tig  = lane & 3;
    const int wr0  = (wid & 1) * 64;      // warp row in block
    const int wc0  = (wid >> 1) * 32;     // warp col in block
    const int row0 = blockIdx.x * 128;
    const int cb   = blockIdx.y * 128;

    float acc[4][4][4];
    #pragma unroll
    for (int mt = 0; mt < 4; mt++)
        #pragma unroll
        for (int nt = 0; nt < 4; nt++)
            #pragma unroll
            for (int e = 0; e < 4; e++) acc[mt][nt][e] = 0.0f;

    float4 areg[2], breg[2];
    {   // prefetch tile 0
        #pragma unroll
        for (int q = 0; q < 2; q++) {
            int idx = tid + q * 256;
            areg[q] = *reinterpret_cast<const float4*>(&X[(row0 + (idx >> 2)) * Dd + (idx & 3) * 4]);
            breg[q] = *reinterpret_cast<const float4*>(&W[(idx >> 5) * Hh + cb + (idx & 31) * 4]);
        }
    }

    #pragma unroll 1
    for (int kt = 0; kt < Dd / 16; kt++) {
        __syncthreads();
        #pragma unroll
        for (int q = 0; q < 2; q++) {
            int idx = tid + q * 256;
            int ar = idx >> 2, ak = (idx & 3) * 4;
            const float av[4] = {areg[q].x, areg[q].y, areg[q].z, areg[q].w};
            #pragma unroll
            for (int j = 0; j < 4; j++)
                tf32_split(av[j], Ah[ak + j][ar], Al[ak + j][ar]);
            int bk = idx >> 5, bc = (idx & 31) * 4;
            const float bv[4] = {breg[q].x, breg[q].y, breg[q].z, breg[q].w};
            uint4 hv, lv;
            tf32_split(bv[0], hv.x, lv.x); tf32_split(bv[1], hv.y, lv.y);
            tf32_split(bv[2], hv.z, lv.z); tf32_split(bv[3], hv.w, lv.w);
            *reinterpret_cast<uint4*>(&Bh[bk][bc]) = hv;
            *reinterpret_cast<uint4*>(&Bl[bk][bc]) = lv;
        }
        __syncthreads();

        if (kt + 1 < Dd / 16) {
            int kn = (kt + 1) * 16;
            #pragma unroll
            for (int q = 0; q < 2; q++) {
                int idx = tid + q * 256;
                areg[q] = *reinterpret_cast<const float4*>(&X[(row0 + (idx >> 2)) * Dd + kn + (idx & 3) * 4]);
                breg[q] = *reinterpret_cast<const float4*>(&W[(kn + (idx >> 5)) * Hh + cb + (idx & 31) * 4]);
            }
        }

        #pragma unroll
        for (int k8 = 0; k8 < 16; k8 += 8) {
            uint32_t ah[4][4], al[4][4], bh[4][2], bl[4][2];
            #pragma unroll
            for (int mt = 0; mt < 4; mt++) {
                int r = wr0 + mt * 16 + gid;
                ah[mt][0] = Ah[k8 + tig][r];     ah[mt][1] = Ah[k8 + tig][r + 8];
                ah[mt][2] = Ah[k8 + tig + 4][r]; ah[mt][3] = Ah[k8 + tig + 4][r + 8];
                al[mt][0] = Al[k8 + tig][r];     al[mt][1] = Al[k8 + tig][r + 8];
                al[mt][2] = Al[k8 + tig + 4][r]; al[mt][3] = Al[k8 + tig + 4][r + 8];
            }
            #pragma unroll
            for (int nt = 0; nt < 4; nt++) {
                int c = wc0 + nt * 8 + gid;
                bh[nt][0] = Bh[k8 + tig][c]; bh[nt][1] = Bh[k8 + tig + 4][c];
                bl[nt][0] = Bl[k8 + tig][c]; bl[nt][1] = Bl[k8 + tig + 4][c];
            }
            #pragma unroll
            for (int mt = 0; mt < 4; mt++)
                #pragma unroll
                for (int nt = 0; nt < 4; nt++) {
                    MMA_TF32(acc[mt][nt], ah[mt], bh[nt]);
                    MMA_TF32(acc[mt][nt], al[mt], bh[nt]);
                    MMA_TF32(acc[mt][nt], ah[mt], bl[nt]);
                }
        }
    }

    #pragma unroll
    for (int mt = 0; mt < 4; mt++)
        #pragma unroll
        for (int nt = 0; nt < 4; nt++) {
            int r = row0 + wr0 + mt * 16 + gid;
            int c = cb + wc0 + nt * 8 + tig * 2;
            float2 v0 = {acc[mt][nt][0], acc[mt][nt][1]};
            float2 v1 = {acc[mt][nt][2], acc[mt][nt][3]};
            *reinterpret_cast<float2*>(&g_pre[side][r][c])     = v0;
            *reinterpret_cast<float2*>(&g_pre[side][r + 8][c]) = v1;
        }
}

// ---------------------------------------------------------------------------
// E1: bias + LayerNorm(256) + exact GELU.  One warp per row.
// grid: (Bsz/8, 2), block 256.
// ---------------------------------------------------------------------------
__global__ __launch_bounds__(256) void k_epi1(
    const float* __restrict__ b1p, const float* __restrict__ b1v,
    const float* __restrict__ lgp, const float* __restrict__ lgv,
    const float* __restrict__ lbp, const float* __restrict__ lbv)
{
    const int side = blockIdx.y;
    const float* __restrict__ b1 = side ? b1v : b1p;
    const float* __restrict__ lg = side ? lgv : lgp;
    const float* __restrict__ lb = side ? lbv : lbp;

    const int lane = threadIdx.x & 31;
    const int wid  = threadIdx.x >> 5;
    const int row  = blockIdx.x * 8 + wid;
    const int c0   = lane * 8;

    float4 v0 = *reinterpret_cast<const float4*>(&g_pre[side][row][c0]);
    float4 v1 = *reinterpret_cast<const float4*>(&g_pre[side][row][c0 + 4]);
    float4 bb0 = *reinterpret_cast<const float4*>(&b1[c0]);
    float4 bb1 = *reinterpret_cast<const float4*>(&b1[c0 + 4]);
    float x[8] = {v0.x + bb0.x, v0.y + bb0.y, v0.z + bb0.z, v0.w + bb0.w,
                  v1.x + bb1.x, v1.y + bb1.y, v1.z + bb1.z, v1.w + bb1.w};

    float s = 0.0f, s2 = 0.0f;
    #pragma unroll
    for (int j = 0; j < 8; j++) { s += x[j]; s2 += x[j] * x[j]; }
    #pragma unroll
    for (int o = 16; o > 0; o >>= 1) {
        s  += __shfl_xor_sync(0xffffffffu, s,  o);
        s2 += __shfl_xor_sync(0xffffffffu, s2, o);
    }
    float mu   = s * (1.0f / 256.0f);
    float var  = s2 * (1.0f / 256.0f) - mu * mu;
    float rstd = rsqrtf(var + 1e-5f);

    float4 g0 = *reinterpret_cast<const float4*>(&lg[c0]);
    float4 g1 = *reinterpret_cast<const float4*>(&lg[c0 + 4]);
    float4 o0 = *reinterpret_cast<const float4*>(&lb[c0]);
    float4 o1 = *reinterpret_cast<const float4*>(&lb[c0 + 4]);
    float gg[8] = {g0.x, g0.y, g0.z, g0.w, g1.x, g1.y, g1.z, g1.w};
    float oo[8] = {o0.x, o0.y, o0.z, o0.w, o1.x, o1.y, o1.z, o1.w};

    float y[8];
    #pragma unroll
    for (int j = 0; j < 8; j++)
        y[j] = gelu_exact((x[j] - mu) * rstd * gg[j] + oo[j]);

    float4 w0 = {y[0], y[1], y[2], y[3]};
    float4 w1 = {y[4], y[5], y[6], y[7]};
    *reinterpret_cast<float4*>(&g_act[side][row][c0])     = w0;
    *reinterpret_cast<float4*>(&g_act[side][row][c0 + 4]) = w1;
}

// ---------------------------------------------------------------------------
// GEMM2: M(B,64) = g_act(B,256) @ W2(256,64) + b2, tf32 3x.
// BM=128, BN=64, BK=16. 256 thr, 8 warps (4m x 2n), warp tile 32x32.
// grid: (M/128, side=2)
// ---------------------------------------------------------------------------
__global__ __launch_bounds__(256) void k_gemm2(
    const float* __restrict__ W2p, const float* __restrict__ W2v,
    const float* __restrict__ b2p, const float* __restrict__ b2v)
{
    const int side = blockIdx.y;
    const float* __restrict__ A  = &g_act[side][0][0];
    const float* __restrict__ W  = side ? W2v : W2p;
    const float* __restrict__ b2 = side ? b2v : b2p;

    __shared__ uint32_t Ah[16][136], Al[16][136], Bh[16][72], Bl[16][72];

    const int tid  = threadIdx.x;
    const int lane = tid & 31;
    const int wid  = tid >> 5;
    const int gid  = lane >> 2;
    const int tig  = lane & 3;
    const int wr0  = (wid & 3) * 32;
    const int wc0  = (wid >> 2) * 32;
    const int row0 = blockIdx.x * 128;

    float acc[2][4][4];
    #pragma unroll
    for (int mt = 0; mt < 2; mt++)
        #pragma unroll
        for (int nt = 0; nt < 4; nt++)
            #pragma unroll
            for (int e = 0; e < 4; e++) acc[mt][nt][e] = 0.0f;

    float4 areg[2], breg;
    #pragma unroll
    for (int q = 0; q < 2; q++) {
        int idx = tid + q * 256;
        areg[q] = *reinterpret_cast<const float4*>(&A[(row0 + (idx >> 2)) * Hh + (idx & 3) * 4]);
    }
    breg = *reinterpret_cast<const float4*>(&W[(tid >> 4) * 64 + (tid & 15) * 4]);

    #pragma unroll 1
    for (int kt = 0; kt < Hh / 16; kt++) {
        __syncthreads();
        #pragma unroll
        for (int q = 0; q < 2; q++) {
            int idx = tid + q * 256;
            int ar = idx >> 2, ak = (idx & 3) * 4;
            const float av[4] = {areg[q].x, areg[q].y, areg[q].z, areg[q].w};
            #pragma unroll
            for (int j = 0; j < 4; j++)
                tf32_split(av[j], Ah[ak + j][ar], Al[ak + j][ar]);
        }
        {
            int bk = tid >> 4, bc = (tid & 15) * 4;
            const float bv[4] = {breg.x, breg.y, breg.z, breg.w};
            uint4 hv, lv;
            tf32_split(bv[0], hv.x, lv.x); tf32_split(bv[1], hv.y, lv.y);
            tf32_split(bv[2], hv.z, lv.z); tf32_split(bv[3], hv.w, lv.w);
            *reinterpret_cast<uint4*>(&Bh[bk][bc]) = hv;
            *reinterpret_cast<uint4*>(&Bl[bk][bc]) = lv;
        }
        __syncthreads();

        if (kt + 1 < Hh / 16) {
            int kn = (kt + 1) * 16;
            #pragma unroll
            for (int q = 0; q < 2; q++) {
                int idx = tid + q * 256;
                areg[q] = *reinterpret_cast<const float4*>(&A[(row0 + (idx >> 2)) * Hh + kn + (idx & 3) * 4]);
            }
            breg = *reinterpret_cast<const float4*>(&W[(kn + (tid >> 4)) * 64 + (tid & 15) * 4]);
        }

        #pragma unroll
        for (int k8 = 0; k8 < 16; k8 += 8) {
            uint32_t ah[2][4], al[2][4], bh[4][2], bl[4][2];
            #pragma unroll
            for (int mt = 0; mt < 2; mt++) {
                int r = wr0 + mt * 16 + gid;
                ah[mt][0] = Ah[k8 + tig][r];     ah[mt][1] = Ah[k8 + tig][r + 8];
                ah[mt][2] = Ah[k8 + tig + 4][r]; ah[mt][3] = Ah[k8 + tig + 4][r + 8];
                al[mt][0] = Al[k8 + tig][r];     al[mt][1] = Al[k8 + tig][r + 8];
                al[mt][2] = Al[k8 + tig + 4][r]; al[mt][3] = Al[k8 + tig + 4][r + 8];
            }
            #pragma unroll
            for (int nt = 0; nt < 4; nt++) {
                int c = wc0 + nt * 8 + gid;
                bh[nt][0] = Bh[k8 + tig][c]; bh[nt][1] = Bh[k8 + tig + 4][c];
                bl[nt][0] = Bl[k8 + tig][c]; bl[nt][1] = Bl[k8 + tig + 4][c];
            }
            #pragma unroll
            for (int mt = 0; mt < 2; mt++)
                #pragma unroll
                for (int nt = 0; nt < 4; nt++) {
                    MMA_TF32(acc[mt][nt], ah[mt], bh[nt]);
                    MMA_TF32(acc[mt][nt], al[mt], bh[nt]);
                    MMA_TF32(acc[mt][nt], ah[mt], bl[nt]);
                }
        }
    }

    #pragma unroll
    for (int mt = 0; mt < 2; mt++)
        #pragma unroll
        for (int nt = 0; nt < 4; nt++) {
            int r = row0 + wr0 + mt * 16 + gid;
            int c = wc0 + nt * 8 + tig * 2;
            float b0 = b2[c], b1b = b2[c + 1];
            float2 v0 = {acc[mt][nt][0] + b0, acc[mt][nt][1] + b1b};
            float2 v1 = {acc[mt][nt][2] + b0, acc[mt][nt][3] + b1b};
            *reinterpret_cast<float2*>(&g_m[side][r][c])     = v0;
            *reinterpret_cast<float2*>(&g_m[side][r + 8][c]) = v1;
        }
}

// ---------------------------------------------------------------------------
// K3: Clifford triple-product collapse + readout vs T.  (unchanged, passing)
// ---------------------------------------------------------------------------
__global__ __launch_bounds__(256) void k3_triple(
    const float* __restrict__ T, const float* __restrict__ gw,
    float* __restrict__ out)
{
    __shared__ float Ts[Rr * 65];
    __shared__ float s_gw[8];
    __shared__ float s_mp[8][64], s_mv[8][64], s_V[8][64], s_Q[8][64];

    const int tid = threadIdx.x;
    const int lane = tid & 31;
    const int w = tid >> 5;

    for (int i = tid; i < Rr * 64; i += 256)
        Ts[(i >> 6) * 65 + (i & 63)] = T[i];
    if (tid < 8) s_gw[tid] = gw[tid];
    __syncthreads();

    const int row = blockIdx.x * 8 + w;

    s_mp[w][lane]      = g_m[0][row][lane];
    s_mp[w][lane + 32] = g_m[0][row][lane + 32];
    s_mv[w][lane]      = g_m[1][row][lane];
    s_mv[w][lane + 32] = g_m[1][row][lane + 32];
    __syncwarp();

    const int MASKS_[8] = {0, 1, 2, 4, 3, 5, 6, 7};

    #pragma unroll
    for (int h = 0; h < 2; h++) {
        int f = lane + h * 32;
        int k = f >> 3, u = f & 7;
        float v = 0.0f;
        #pragma unroll
        for (int jm = 0; jm < 8; jm++) {
            int mj = MASKS_[jm];
            v += s_mv[w][k * 8 + jm] * csign(u, mj) * s_gw[cidx(u ^ mj)];
        }
        s_V[w][f] = v;
    }
    __syncwarp();

    #pragma unroll
    for (int h = 0; h < 2; h++) {
        int f = lane + h * 32;
        int k = f >> 3, jc = f & 7;
        int mjc = MASKS_[jc];
        float q = 0.0f;
        #pragma unroll
        for (int i = 0; i < 8; i++) {
            int mi = MASKS_[i];
            q += s_mp[w][k * 8 + i] * csign(mi, mjc) * s_V[w][k * 8 + (mi ^ mjc)];
        }
        s_Q[w][f] = q;
    }
    __syncwarp();

    #pragma unroll
    for (int h = 0; h < 3; h++) {
        int r = lane + h * 32;
        if (r < Rr) {
            float a = 0.0f;
            #pragma unroll
            for (int f = 0; f < 64; f++)
                a = fmaf(Ts[r * 65 + f], s_Q[w][f], a);
            out[row * Rr + r] = a * 0.125f;
        }
    }
}

// ---------------------------------------------------------------------------
extern "C" void kernel_launch(void* const* d_in, const int* in_sizes, int n_in,
                              void* d_out, int out_size)
{
    const float* h_perp = (const float*)d_in[0];
    const float* h_vuln = (const float*)d_in[1];
    const float* Wp1    = (const float*)d_in[2];
    const float* bp1    = (const float*)d_in[3];
    const float* lgp    = (const float*)d_in[4];
    const float* lbp    = (const float*)d_in[5];
    const float* Wp2    = (const float*)d_in[6];
    const float* bp2    = (const float*)d_in[7];
    const float* Wv1    = (const float*)d_in[8];
    const float* bv1    = (const float*)d_in[9];
    const float* lgv    = (const float*)d_in[10];
    const float* lbv    = (const float*)d_in[11];
    const float* Wv2    = (const float*)d_in[12];
    const float* bv2    = (const float*)d_in[13];
    const float* T      = (const float*)d_in[14];
    const float* gw     = (const float*)d_in[15];
    float* out = (float*)d_out;

    k_gemm1<<<dim3(Bsz / 128, Hh / 128, 2), 256>>>(h_perp, h_vuln, Wp1, Wv1);
    k_epi1<<<dim3(Bsz / 8, 2), 256>>>(bp1, bv1, lgp, lgv, lbp, lbv);
    k_gemm2<<<dim3(Bsz / 128, 2), 256>>>(Wp2, Wv2, bp2, bv2);
    k3_triple<<<Bsz / 8, 256>>>(T, gw, out);
}

// round 6
// speedup vs baseline: 3.8307x; 1.5645x over previous
#include <cuda_runtime.h>
#include <cuda_bf16.h>
#include <stdint.h>

#define Bsz 16384
#define Dd 512
#define Hh 256
#define Rr 95

// ------------------------------- scratch -----------------------------------
__device__ float    g_pre[2][Bsz][Hh];        // pre-LN GEMM1 output (fp32)
__device__ uint32_t g_acth[2][Bsz][Hh / 2];   // post-GELU acts, bf16x2 hi (k-pairs)
__device__ uint32_t g_actl[2][Bsz][Hh / 2];   // post-GELU acts, bf16x2 lo
__device__ float    g_m[2][Bsz][64];          // mp / mv multivectors
__device__ uint32_t g_W1s[2][2][Dd / 2][Hh];  // [side][hi/lo][k2][n] packed bf16x2
__device__ uint32_t g_W2s[2][2][Hh / 2][64];  // [side][hi/lo][k2][n]

// ------------------------------- helpers -----------------------------------
__device__ __forceinline__ float gelu_exact(float x) {
    return 0.5f * x * (1.0f + erff(x * 0.70710678118654752440f));
}
__device__ __forceinline__ float csign(int a, int b) {
    int sw = __popc((a >> 1) & b) + __popc((a >> 2) & b);
    return (sw & 1) ? -1.0f : 1.0f;
}
__device__ __forceinline__ int cidx(int m) { return m + (m == 3) - (m == 4); }

// split 2 fp32 into packed bf16x2 (hi) and packed bf16x2 (residual lo)
__device__ __forceinline__ void bf16_split_pack(float x0, float x1,
                                                uint32_t& hp, uint32_t& lp) {
    __nv_bfloat16 h0 = __float2bfloat16(x0), h1 = __float2bfloat16(x1);
    float r0 = x0 - __bfloat162float(h0);
    float r1 = x1 - __bfloat162float(h1);
    __nv_bfloat16 l0 = __float2bfloat16(r0), l1 = __float2bfloat16(r1);
    hp = ((uint32_t)__bfloat16_as_ushort(h1) << 16) | (uint32_t)__bfloat16_as_ushort(h0);
    lp = ((uint32_t)__bfloat16_as_ushort(l1) << 16) | (uint32_t)__bfloat16_as_ushort(l0);
}

#define MMA_BF16(d, a, b) \
    asm volatile("mma.sync.aligned.m16n8k16.row.col.f32.bf16.bf16.f32 " \
        "{%0,%1,%2,%3}, {%4,%5,%6,%7}, {%8,%9}, {%0,%1,%2,%3};" \
        : "+f"(d[0]), "+f"(d[1]), "+f"(d[2]), "+f"(d[3]) \
        : "r"(a[0]), "r"(a[1]), "r"(a[2]), "r"(a[3]), "r"(b[0]), "r"(b[1]))

// ---------------------------------------------------------------------------
// prep: W1(512,256) -> g_W1s[side][h][k2][n] packed bf16x2 (pairs along k)
// ---------------------------------------------------------------------------
__global__ __launch_bounds__(256) void k_prep_w1(
    const float* __restrict__ W1p, const float* __restrict__ W1v)
{
    int idx  = blockIdx.x * 256 + threadIdx.x;   // 2 * 256 * 256
    int side = idx >> 16;
    int rem  = idx & 0xFFFF;
    int k2   = rem >> 8;
    int n    = rem & 255;
    const float* W = side ? W1v : W1p;
    float x0 = __ldg(&W[(2 * k2) * Hh + n]);
    float x1 = __ldg(&W[(2 * k2 + 1) * Hh + n]);
    uint32_t hp, lp;
    bf16_split_pack(x0, x1, hp, lp);
    g_W1s[side][0][k2][n] = hp;
    g_W1s[side][1][k2][n] = lp;
}

// prep: W2(256,64) -> g_W2s[side][h][k2][n]
__global__ __launch_bounds__(256) void k_prep_w2(
    const float* __restrict__ W2p, const float* __restrict__ W2v)
{
    int idx  = blockIdx.x * 256 + threadIdx.x;   // 2 * 128 * 64
    int side = idx >> 13;
    int rem  = idx & 0x1FFF;
    int k2   = rem >> 6;
    int n    = rem & 63;
    const float* W = side ? W2v : W2p;
    float x0 = __ldg(&W[(2 * k2) * 64 + n]);
    float x1 = __ldg(&W[(2 * k2 + 1) * 64 + n]);
    uint32_t hp, lp;
    bf16_split_pack(x0, x1, hp, lp);
    g_W2s[side][0][k2][n] = hp;
    g_W2s[side][1][k2][n] = lp;
}

// ---------------------------------------------------------------------------
// GEMM1: Y(B,256) = X(B,512) @ W1(512,256), bf16 3x (m16n8k16).
// BM=128, BN=128, BK=32 (16 k2). 256 thr, 8 warps (2m x 4n), warp tile 64x32.
// grid: (M/128, N/128=2, side=2)
// ---------------------------------------------------------------------------
__global__ __launch_bounds__(256) void k_gemm1(
    const float* __restrict__ Xp, const float* __restrict__ Xv)
{
    const int side = blockIdx.z;
    const float* __restrict__ X = side ? Xv : Xp;

    __shared__ uint32_t Ah[16][136], Al[16][136], Bh[16][136], Bl[16][136];

    const int tid  = threadIdx.x;
    const int lane = tid & 31;
    const int wid  = tid >> 5;
    const int gid  = lane >> 2;
    const int tig  = lane & 3;
    const int wr0  = (wid & 1) * 64;
    const int wc0  = (wid >> 1) * 32;
    const int row0 = blockIdx.x * 128;
    const int cb   = blockIdx.y * 128;

    float acc[4][4][4];
    #pragma unroll
    for (int mt = 0; mt < 4; mt++)
        #pragma unroll
        for (int nt = 0; nt < 4; nt++)
            #pragma unroll
            for (int e = 0; e < 4; e++) acc[mt][nt][e] = 0.0f;

    float4 areg[4];
    uint4  bhreg[2], blreg[2];
    #pragma unroll
    for (int q = 0; q < 4; q++) {
        int idx = tid + q * 256;
        areg[q] = *reinterpret_cast<const float4*>(&X[(row0 + (idx >> 3)) * Dd + (idx & 7) * 4]);
    }
    #pragma unroll
    for (int q = 0; q < 2; q++) {
        int idx = tid + q * 256;
        int k2l = idx >> 5, n4 = (idx & 31) * 4;
        bhreg[q] = *reinterpret_cast<const uint4*>(&g_W1s[side][0][k2l][cb + n4]);
        blreg[q] = *reinterpret_cast<const uint4*>(&g_W1s[side][1][k2l][cb + n4]);
    }

    #pragma unroll 1
    for (int kt = 0; kt < 16; kt++) {
        __syncthreads();
        #pragma unroll
        for (int q = 0; q < 4; q++) {
            int idx = tid + q * 256;
            int row = idx >> 3, k2 = (idx & 7) * 2;
            bf16_split_pack(areg[q].x, areg[q].y, Ah[k2][row],     Al[k2][row]);
            bf16_split_pack(areg[q].z, areg[q].w, Ah[k2 + 1][row], Al[k2 + 1][row]);
        }
        #pragma unroll
        for (int q = 0; q < 2; q++) {
            int idx = tid + q * 256;
            int k2l = idx >> 5, n4 = (idx & 31) * 4;
            *reinterpret_cast<uint4*>(&Bh[k2l][n4]) = bhreg[q];
            *reinterpret_cast<uint4*>(&Bl[k2l][n4]) = blreg[q];
        }
        __syncthreads();

        if (kt + 1 < 16) {
            int kn = (kt + 1) * 32;
            #pragma unroll
            for (int q = 0; q < 4; q++) {
                int idx = tid + q * 256;
                areg[q] = *reinterpret_cast<const float4*>(
                    &X[(row0 + (idx >> 3)) * Dd + kn + (idx & 7) * 4]);
            }
            int k2n = (kt + 1) * 16;
            #pragma unroll
            for (int q = 0; q < 2; q++) {
                int idx = tid + q * 256;
                int k2l = idx >> 5, n4 = (idx & 31) * 4;
                bhreg[q] = *reinterpret_cast<const uint4*>(&g_W1s[side][0][k2n + k2l][cb + n4]);
                blreg[q] = *reinterpret_cast<const uint4*>(&g_W1s[side][1][k2n + k2l][cb + n4]);
            }
        }

        #pragma unroll
        for (int k8x = 0; k8x < 16; k8x += 8) {
            uint32_t ah[4][4], al[4][4], bh[4][2], bl[4][2];
            #pragma unroll
            for (int mt = 0; mt < 4; mt++) {
                int r = wr0 + mt * 16 + gid;
                ah[mt][0] = Ah[k8x + tig][r];     ah[mt][1] = Ah[k8x + tig][r + 8];
                ah[mt][2] = Ah[k8x + tig + 4][r]; ah[mt][3] = Ah[k8x + tig + 4][r + 8];
                al[mt][0] = Al[k8x + tig][r];     al[mt][1] = Al[k8x + tig][r + 8];
                al[mt][2] = Al[k8x + tig + 4][r]; al[mt][3] = Al[k8x + tig + 4][r + 8];
            }
            #pragma unroll
            for (int nt = 0; nt < 4; nt++) {
                int c = wc0 + nt * 8 + gid;
                bh[nt][0] = Bh[k8x + tig][c]; bh[nt][1] = Bh[k8x + tig + 4][c];
                bl[nt][0] = Bl[k8x + tig][c]; bl[nt][1] = Bl[k8x + tig + 4][c];
            }
            #pragma unroll
            for (int mt = 0; mt < 4; mt++)
                #pragma unroll
                for (int nt = 0; nt < 4; nt++) {
                    MMA_BF16(acc[mt][nt], ah[mt], bh[nt]);
                    MMA_BF16(acc[mt][nt], al[mt], bh[nt]);
                    MMA_BF16(acc[mt][nt], ah[mt], bl[nt]);
                }
        }
    }

    #pragma unroll
    for (int mt = 0; mt < 4; mt++)
        #pragma unroll
        for (int nt = 0; nt < 4; nt++) {
            int r = row0 + wr0 + mt * 16 + gid;
            int c = cb + wc0 + nt * 8 + tig * 2;
            float2 v0 = {acc[mt][nt][0], acc[mt][nt][1]};
            float2 v1 = {acc[mt][nt][2], acc[mt][nt][3]};
            *reinterpret_cast<float2*>(&g_pre[side][r][c])     = v0;
            *reinterpret_cast<float2*>(&g_pre[side][r + 8][c]) = v1;
        }
}

// ---------------------------------------------------------------------------
// E1: bias + LayerNorm(256) + exact GELU; writes packed bf16 hi/lo acts.
// One warp per row. grid (Bsz/8, 2), block 256.
// ---------------------------------------------------------------------------
__global__ __launch_bounds__(256) void k_epi1(
    const float* __restrict__ b1p, const float* __restrict__ b1v,
    const float* __restrict__ lgp, const float* __restrict__ lgv,
    const float* __restrict__ lbp, const float* __restrict__ lbv)
{
    const int side = blockIdx.y;
    const float* __restrict__ b1 = side ? b1v : b1p;
    const float* __restrict__ lg = side ? lgv : lgp;
    const float* __restrict__ lb = side ? lbv : lbp;

    const int lane = threadIdx.x & 31;
    const int wid  = threadIdx.x >> 5;
    const int row  = blockIdx.x * 8 + wid;
    const int c0   = lane * 8;

    float4 v0 = *reinterpret_cast<const float4*>(&g_pre[side][row][c0]);
    float4 v1 = *reinterpret_cast<const float4*>(&g_pre[side][row][c0 + 4]);
    float4 bb0 = *reinterpret_cast<const float4*>(&b1[c0]);
    float4 bb1 = *reinterpret_cast<const float4*>(&b1[c0 + 4]);
    float x[8] = {v0.x + bb0.x, v0.y + bb0.y, v0.z + bb0.z, v0.w + bb0.w,
                  v1.x + bb1.x, v1.y + bb1.y, v1.z + bb1.z, v1.w + bb1.w};

    float s = 0.0f, s2 = 0.0f;
    #pragma unroll
    for (int j = 0; j < 8; j++) { s += x[j]; s2 += x[j] * x[j]; }
    #pragma unroll
    for (int o = 16; o > 0; o >>= 1) {
        s  += __shfl_xor_sync(0xffffffffu, s,  o);
        s2 += __shfl_xor_sync(0xffffffffu, s2, o);
    }
    float mu   = s * (1.0f / 256.0f);
    float var  = s2 * (1.0f / 256.0f) - mu * mu;
    float rstd = rsqrtf(var + 1e-5f);

    float4 g0 = *reinterpret_cast<const float4*>(&lg[c0]);
    float4 g1 = *reinterpret_cast<const float4*>(&lg[c0 + 4]);
    float4 o0 = *reinterpret_cast<const float4*>(&lb[c0]);
    float4 o1 = *reinterpret_cast<const float4*>(&lb[c0 + 4]);
    float gg[8] = {g0.x, g0.y, g0.z, g0.w, g1.x, g1.y, g1.z, g1.w};
    float oo[8] = {o0.x, o0.y, o0.z, o0.w, o1.x, o1.y, o1.z, o1.w};

    float y[8];
    #pragma unroll
    for (int j = 0; j < 8; j++)
        y[j] = gelu_exact((x[j] - mu) * rstd * gg[j] + oo[j]);

    uint4 hv, lv;
    bf16_split_pack(y[0], y[1], hv.x, lv.x);
    bf16_split_pack(y[2], y[3], hv.y, lv.y);
    bf16_split_pack(y[4], y[5], hv.z, lv.z);
    bf16_split_pack(y[6], y[7], hv.w, lv.w);
    *reinterpret_cast<uint4*>(&g_acth[side][row][lane * 4]) = hv;
    *reinterpret_cast<uint4*>(&g_actl[side][row][lane * 4]) = lv;
}

// ---------------------------------------------------------------------------
// GEMM2: M(B,64) = act(B,256) @ W2(256,64) + b2, bf16 3x. Inputs pre-split.
// BM=128, BN=64, BK=32 (16 k2). 256 thr, 8 warps (4m x 2n), warp tile 32x32.
// ---------------------------------------------------------------------------
__global__ __launch_bounds__(256, 2) void k_gemm2(
    const float* __restrict__ b2p, const float* __restrict__ b2v)
{
    const int side = blockIdx.y;
    const float* __restrict__ b2 = side ? b2v : b2p;

    __shared__ uint32_t Ah[128][20], Al[128][20], Bh[16][72], Bl[16][72];

    const int tid  = threadIdx.x;
    const int lane = tid & 31;
    const int wid  = tid >> 5;
    const int gid  = lane >> 2;
    const int tig  = lane & 3;
    const int wr0  = (wid & 3) * 32;
    const int wc0  = (wid >> 2) * 32;
    const int row0 = blockIdx.x * 128;

    float acc[2][4][4];
    #pragma unroll
    for (int mt = 0; mt < 2; mt++)
        #pragma unroll
        for (int nt = 0; nt < 4; nt++)
            #pragma unroll
            for (int e = 0; e < 4; e++) acc[mt][nt][e] = 0.0f;

    uint4 ahreg[2], alreg[2], bhreg, blreg;
    #pragma unroll
    for (int q = 0; q < 2; q++) {
        int idx = tid + q * 256;
        int row = idx >> 2, k2q = (idx & 3) * 4;
        ahreg[q] = *reinterpret_cast<const uint4*>(&g_acth[side][row0 + row][k2q]);
        alreg[q] = *reinterpret_cast<const uint4*>(&g_actl[side][row0 + row][k2q]);
    }
    {
        int k2l = tid >> 4, n4 = (tid & 15) * 4;
        bhreg = *reinterpret_cast<const uint4*>(&g_W2s[side][0][k2l][n4]);
        blreg = *reinterpret_cast<const uint4*>(&g_W2s[side][1][k2l][n4]);
    }

    #pragma unroll 1
    for (int kt = 0; kt < 8; kt++) {
        __syncthreads();
        #pragma unroll
        for (int q = 0; q < 2; q++) {
            int idx = tid + q * 256;
            int row = idx >> 2, k2q = (idx & 3) * 4;
            *reinterpret_cast<uint4*>(&Ah[row][k2q]) = ahreg[q];
            *reinterpret_cast<uint4*>(&Al[row][k2q]) = alreg[q];
        }
        {
            int k2l = tid >> 4, n4 = (tid & 15) * 4;
            *reinterpret_cast<uint4*>(&Bh[k2l][n4]) = bhreg;
            *reinterpret_cast<uint4*>(&Bl[k2l][n4]) = blreg;
        }
        __syncthreads();

        if (kt + 1 < 8) {
            int k2n = (kt + 1) * 16;
            #pragma unroll
            for (int q = 0; q < 2; q++) {
                int idx = tid + q * 256;
                int row = idx >> 2, k2q = (idx & 3) * 4;
                ahreg[q] = *reinterpret_cast<const uint4*>(&g_acth[side][row0 + row][k2n + k2q]);
                alreg[q] = *reinterpret_cast<const uint4*>(&g_actl[side][row0 + row][k2n + k2q]);
            }
            int k2l = tid >> 4, n4 = (tid & 15) * 4;
            bhreg = *reinterpret_cast<const uint4*>(&g_W2s[side][0][k2n + k2l][n4]);
            blreg = *reinterpret_cast<const uint4*>(&g_W2s[side][1][k2n + k2l][n4]);
        }

        #pragma unroll
        for (int k8x = 0; k8x < 16; k8x += 8) {
            uint32_t ah[2][4], al2[2][4], bh[4][2], bl[4][2];
            #pragma unroll
            for (int mt = 0; mt < 2; mt++) {
                int r = wr0 + mt * 16 + gid;
                ah[mt][0] = Ah[r][k8x + tig];     ah[mt][1] = Ah[r + 8][k8x + tig];
                ah[mt][2] = Ah[r][k8x + tig + 4]; ah[mt][3] = Ah[r + 8][k8x + tig + 4];
                al2[mt][0] = Al[r][k8x + tig];     al2[mt][1] = Al[r + 8][k8x + tig];
                al2[mt][2] = Al[r][k8x + tig + 4]; al2[mt][3] = Al[r + 8][k8x + tig + 4];
            }
            #pragma unroll
            for (int nt = 0; nt < 4; nt++) {
                int c = wc0 + nt * 8 + gid;
                bh[nt][0] = Bh[k8x + tig][c]; bh[nt][1] = Bh[k8x + tig + 4][c];
                bl[nt][0] = Bl[k8x + tig][c]; bl[nt][1] = Bl[k8x + tig + 4][c];
            }
            #pragma unroll
            for (int mt = 0; mt < 2; mt++)
                #pragma unroll
                for (int nt = 0; nt < 4; nt++) {
                    MMA_BF16(acc[mt][nt], ah[mt], bh[nt]);
                    MMA_BF16(acc[mt][nt], al2[mt], bh[nt]);
                    MMA_BF16(acc[mt][nt], ah[mt], bl[nt]);
                }
        }
    }

    #pragma unroll
    for (int mt = 0; mt < 2; mt++)
        #pragma unroll
        for (int nt = 0; nt < 4; nt++) {
            int r = row0 + wr0 + mt * 16 + gid;
            int c = wc0 + nt * 8 + tig * 2;
            float b0 = b2[c], b1b = b2[c + 1];
            float2 v0 = {acc[mt][nt][0] + b0, acc[mt][nt][1] + b1b};
            float2 v1 = {acc[mt][nt][2] + b0, acc[mt][nt][3] + b1b};
            *reinterpret_cast<float2*>(&g_m[side][r][c])     = v0;
            *reinterpret_cast<float2*>(&g_m[side][r + 8][c]) = v1;
        }
}

// ---------------------------------------------------------------------------
// K3: Clifford triple-product collapse + readout vs T (unchanged, passing)
// ---------------------------------------------------------------------------
__global__ __launch_bounds__(256) void k3_triple(
    const float* __restrict__ T, const float* __restrict__ gw,
    float* __restrict__ out)
{
    __shared__ float Ts[Rr * 65];
    __shared__ float s_gw[8];
    __shared__ float s_mp[8][64], s_mv[8][64], s_V[8][64], s_Q[8][64];

    const int tid = threadIdx.x;
    const int lane = tid & 31;
    const int w = tid >> 5;

    for (int i = tid; i < Rr * 64; i += 256)
        Ts[(i >> 6) * 65 + (i & 63)] = T[i];
    if (tid < 8) s_gw[tid] = gw[tid];
    __syncthreads();

    const int row = blockIdx.x * 8 + w;

    s_mp[w][lane]      = g_m[0][row][lane];
    s_mp[w][lane + 32] = g_m[0][row][lane + 32];
    s_mv[w][lane]      = g_m[1][row][lane];
    s_mv[w][lane + 32] = g_m[1][row][lane + 32];
    __syncwarp();

    const int MASKS_[8] = {0, 1, 2, 4, 3, 5, 6, 7};

    #pragma unroll
    for (int h = 0; h < 2; h++) {
        int f = lane + h * 32;
        int k = f >> 3, u = f & 7;
        float v = 0.0f;
        #pragma unroll
        for (int jm = 0; jm < 8; jm++) {
            int mj = MASKS_[jm];
            v += s_mv[w][k * 8 + jm] * csign(u, mj) * s_gw[cidx(u ^ mj)];
        }
        s_V[w][f] = v;
    }
    __syncwarp();

    #pragma unroll
    for (int h = 0; h < 2; h++) {
        int f = lane + h * 32;
        int k = f >> 3, jc = f & 7;
        int mjc = MASKS_[jc];
        float q = 0.0f;
        #pragma unroll
        for (int i = 0; i < 8; i++) {
            int mi = MASKS_[i];
            q += s_mp[w][k * 8 + i] * csign(mi, mjc) * s_V[w][k * 8 + (mi ^ mjc)];
        }
        s_Q[w][f] = q;
    }
    __syncwarp();

    #pragma unroll
    for (int h = 0; h < 3; h++) {
        int r = lane + h * 32;
        if (r < Rr) {
            float a = 0.0f;
            #pragma unroll
            for (int f = 0; f < 64; f++)
                a = fmaf(Ts[r * 65 + f], s_Q[w][f], a);
            out[row * Rr + r] = a * 0.125f;
        }
    }
}

// ---------------------------------------------------------------------------
extern "C" void kernel_launch(void* const* d_in, const int* in_sizes, int n_in,
                              void* d_out, int out_size)
{
    const float* h_perp = (const float*)d_in[0];
    const float* h_vuln = (const float*)d_in[1];
    const float* Wp1    = (const float*)d_in[2];
    const float* bp1    = (const float*)d_in[3];
    const float* lgp    = (const float*)d_in[4];
    const float* lbp    = (const float*)d_in[5];
    const float* Wp2    = (const float*)d_in[6];
    const float* bp2    = (const float*)d_in[7];
    const float* Wv1    = (const float*)d_in[8];
    const float* bv1    = (const float*)d_in[9];
    const float* lgv    = (const float*)d_in[10];
    const float* lbv    = (const float*)d_in[11];
    const float* Wv2    = (const float*)d_in[12];
    const float* bv2    = (const float*)d_in[13];
    const float* T      = (const float*)d_in[14];
    const float* gw     = (const float*)d_in[15];
    float* out = (float*)d_out;

    k_prep_w1<<<(2 * (Dd / 2) * Hh) / 256, 256>>>(Wp1, Wv1);
    k_prep_w2<<<(2 * (Hh / 2) * 64) / 256, 256>>>(Wp2, Wv2);
    k_gemm1<<<dim3(Bsz / 128, Hh / 128, 2), 256>>>(h_perp, h_vuln);
    k_epi1<<<dim3(Bsz / 8, 2), 256>>>(bp1, bv1, lgp, lgv, lbp, lbv);
    k_gemm2<<<dim3(Bsz / 128, 2), 256>>>(bp2, bv2);
    k3_triple<<<Bsz / 8, 256>>>(T, gw, out);
}

// round 7
// speedup vs baseline: 3.9254x; 1.0247x over previous
#include <cuda_runtime.h>
#include <cuda_bf16.h>
#include <stdint.h>

#define Bsz 16384
#define Dd 512
#define Hh 256
#define Rr 95

// ------------------------------- scratch -----------------------------------
__device__ uint32_t g_acth[2][Bsz][Hh / 2];   // post-GELU acts, bf16x2 hi
__device__ uint32_t g_actl[2][Bsz][Hh / 2];   // post-GELU acts, bf16x2 lo
__device__ float    g_m[2][Bsz][64];          // mp / mv multivectors
__device__ uint32_t g_W1s[2][2][Dd / 2][Hh];  // [side][hi/lo][k2][n]
__device__ uint32_t g_W2s[2][2][Hh / 2][64];
__device__ uint32_t g_Qh[Bsz][32];            // Q collapsed, bf16x2 hi (k2)
__device__ uint32_t g_Ql[Bsz][32];
__device__ uint32_t g_Th[32][128];            // T*0.125 pre-split [k2][n(pad 128)]
__device__ uint32_t g_Tl[32][128];

// ------------------------------- helpers -----------------------------------
__device__ __forceinline__ float gelu_exact(float x) {
    return 0.5f * x * (1.0f + erff(x * 0.70710678118654752440f));
}
__device__ __forceinline__ float csign(int a, int b) {
    int sw = __popc((a >> 1) & b) + __popc((a >> 2) & b);
    return (sw & 1) ? -1.0f : 1.0f;
}
__device__ __forceinline__ int cidx(int m) { return m + (m == 3) - (m == 4); }

__device__ __forceinline__ void bf16_split_pack(float x0, float x1,
                                                uint32_t& hp, uint32_t& lp) {
    __nv_bfloat16 h0 = __float2bfloat16(x0), h1 = __float2bfloat16(x1);
    float r0 = x0 - __bfloat162float(h0);
    float r1 = x1 - __bfloat162float(h1);
    __nv_bfloat16 l0 = __float2bfloat16(r0), l1 = __float2bfloat16(r1);
    hp = ((uint32_t)__bfloat16_as_ushort(h1) << 16) | (uint32_t)__bfloat16_as_ushort(h0);
    lp = ((uint32_t)__bfloat16_as_ushort(l1) << 16) | (uint32_t)__bfloat16_as_ushort(l0);
}

#define MMA_BF16(d, a, b) \
    asm volatile("mma.sync.aligned.m16n8k16.row.col.f32.bf16.bf16.f32 " \
        "{%0,%1,%2,%3}, {%4,%5,%6,%7}, {%8,%9}, {%0,%1,%2,%3};" \
        : "+f"(d[0]), "+f"(d[1]), "+f"(d[2]), "+f"(d[3]) \
        : "r"(a[0]), "r"(a[1]), "r"(a[2]), "r"(a[3]), "r"(b[0]), "r"(b[1]))

// ---------------------------------------------------------------------------
// preps
// ---------------------------------------------------------------------------
__global__ __launch_bounds__(256) void k_prep_w1(
    const float* __restrict__ W1p, const float* __restrict__ W1v)
{
    int idx  = blockIdx.x * 256 + threadIdx.x;   // 2 * 256 * 256
    int side = idx >> 16;
    int rem  = idx & 0xFFFF;
    int k2   = rem >> 8;
    int n    = rem & 255;
    const float* W = side ? W1v : W1p;
    float x0 = __ldg(&W[(2 * k2) * Hh + n]);
    float x1 = __ldg(&W[(2 * k2 + 1) * Hh + n]);
    uint32_t hp, lp;
    bf16_split_pack(x0, x1, hp, lp);
    g_W1s[side][0][k2][n] = hp;
    g_W1s[side][1][k2][n] = lp;
}

__global__ __launch_bounds__(256) void k_prep_w2(
    const float* __restrict__ W2p, const float* __restrict__ W2v)
{
    int idx  = blockIdx.x * 256 + threadIdx.x;   // 2 * 128 * 64
    int side = idx >> 13;
    int rem  = idx & 0x1FFF;
    int k2   = rem >> 6;
    int n    = rem & 63;
    const float* W = side ? W2v : W2p;
    float x0 = __ldg(&W[(2 * k2) * 64 + n]);
    float x1 = __ldg(&W[(2 * k2 + 1) * 64 + n]);
    uint32_t hp, lp;
    bf16_split_pack(x0, x1, hp, lp);
    g_W2s[side][0][k2][n] = hp;
    g_W2s[side][1][k2][n] = lp;
}

// T(95,64) -> g_T[k2][n pad 128], pre-scaled by 1/8
__global__ __launch_bounds__(256) void k_prep_T(const float* __restrict__ T)
{
    int idx = blockIdx.x * 256 + threadIdx.x;    // 32 * 128
    int k2 = idx >> 7;
    int n  = idx & 127;
    float x0 = 0.0f, x1 = 0.0f;
    if (n < Rr) {
        x0 = __ldg(&T[n * 64 + 2 * k2])     * 0.125f;
        x1 = __ldg(&T[n * 64 + 2 * k2 + 1]) * 0.125f;
    }
    uint32_t hp, lp;
    bf16_split_pack(x0, x1, hp, lp);
    g_Th[k2][n] = hp;
    g_Tl[k2][n] = lp;
}

// ---------------------------------------------------------------------------
// GEMM1 fused: Y = X(B,512)@W1 + b1 -> LN -> GELU -> split acts.
// BM=64, BN=256 (full row), BK=32. 8 warps, warp tile 64x32 (wc0=wid*32).
// grid (Bsz/64, 2 sides)
// ---------------------------------------------------------------------------
__global__ __launch_bounds__(256) void k_gemm1f(
    const float* __restrict__ Xp, const float* __restrict__ Xv,
    const float* __restrict__ b1p, const float* __restrict__ b1v,
    const float* __restrict__ lgp, const float* __restrict__ lgv,
    const float* __restrict__ lbp, const float* __restrict__ lbv)
{
    const int side = blockIdx.y;
    const float* __restrict__ X  = side ? Xv : Xp;
    const float* __restrict__ b1 = side ? b1v : b1p;
    const float* __restrict__ lg = side ? lgv : lgp;
    const float* __restrict__ lb = side ? lbv : lbp;

    __shared__ uint32_t Ah[16][72], Al[16][72], Bh[16][264], Bl[16][264];
    __shared__ float2 s_part[8][64];
    __shared__ float2 s_ln[64];

    const int tid  = threadIdx.x;
    const int lane = tid & 31;
    const int wid  = tid >> 5;
    const int gid  = lane >> 2;
    const int tig  = lane & 3;
    const int wc0  = wid * 32;
    const int row0 = blockIdx.x * 64;

    float acc[4][4][4];
    #pragma unroll
    for (int mt = 0; mt < 4; mt++)
        #pragma unroll
        for (int nt = 0; nt < 4; nt++)
            #pragma unroll
            for (int e = 0; e < 4; e++) acc[mt][nt][e] = 0.0f;

    float4 areg[2];
    uint4  bhreg[4], blreg[4];
    #pragma unroll
    for (int q = 0; q < 2; q++) {
        int idx = tid + q * 256;
        areg[q] = *reinterpret_cast<const float4*>(&X[(row0 + (idx >> 3)) * Dd + (idx & 7) * 4]);
    }
    #pragma unroll
    for (int q = 0; q < 4; q++) {
        int idx = tid + q * 256;
        int k2l = idx >> 6, n4 = (idx & 63) * 4;
        bhreg[q] = *reinterpret_cast<const uint4*>(&g_W1s[side][0][k2l][n4]);
        blreg[q] = *reinterpret_cast<const uint4*>(&g_W1s[side][1][k2l][n4]);
    }

    #pragma unroll 1
    for (int kt = 0; kt < 16; kt++) {
        __syncthreads();
        #pragma unroll
        for (int q = 0; q < 2; q++) {
            int idx = tid + q * 256;
            int row = idx >> 3, k2 = (idx & 7) * 2;
            bf16_split_pack(areg[q].x, areg[q].y, Ah[k2][row],     Al[k2][row]);
            bf16_split_pack(areg[q].z, areg[q].w, Ah[k2 + 1][row], Al[k2 + 1][row]);
        }
        #pragma unroll
        for (int q = 0; q < 4; q++) {
            int idx = tid + q * 256;
            int k2l = idx >> 6, n4 = (idx & 63) * 4;
            *reinterpret_cast<uint4*>(&Bh[k2l][n4]) = bhreg[q];
            *reinterpret_cast<uint4*>(&Bl[k2l][n4]) = blreg[q];
        }
        __syncthreads();

        if (kt + 1 < 16) {
            int kn = (kt + 1) * 32;
            #pragma unroll
            for (int q = 0; q < 2; q++) {
                int idx = tid + q * 256;
                areg[q] = *reinterpret_cast<const float4*>(
                    &X[(row0 + (idx >> 3)) * Dd + kn + (idx & 7) * 4]);
            }
            int k2n = (kt + 1) * 16;
            #pragma unroll
            for (int q = 0; q < 4; q++) {
                int idx = tid + q * 256;
                int k2l = idx >> 6, n4 = (idx & 63) * 4;
                bhreg[q] = *reinterpret_cast<const uint4*>(&g_W1s[side][0][k2n + k2l][n4]);
                blreg[q] = *reinterpret_cast<const uint4*>(&g_W1s[side][1][k2n + k2l][n4]);
            }
        }

        #pragma unroll
        for (int k8x = 0; k8x < 16; k8x += 8) {
            uint32_t ah[4][4], al[4][4], bh[4][2], bl[4][2];
            #pragma unroll
            for (int mt = 0; mt < 4; mt++) {
                int r = mt * 16 + gid;
                ah[mt][0] = Ah[k8x + tig][r];     ah[mt][1] = Ah[k8x + tig][r + 8];
                ah[mt][2] = Ah[k8x + tig + 4][r]; ah[mt][3] = Ah[k8x + tig + 4][r + 8];
                al[mt][0] = Al[k8x + tig][r];     al[mt][1] = Al[k8x + tig][r + 8];
                al[mt][2] = Al[k8x + tig + 4][r]; al[mt][3] = Al[k8x + tig + 4][r + 8];
            }
            #pragma unroll
            for (int nt = 0; nt < 4; nt++) {
                int c = wc0 + nt * 8 + gid;
                bh[nt][0] = Bh[k8x + tig][c]; bh[nt][1] = Bh[k8x + tig + 4][c];
                bl[nt][0] = Bl[k8x + tig][c]; bl[nt][1] = Bl[k8x + tig + 4][c];
            }
            #pragma unroll
            for (int mt = 0; mt < 4; mt++)
                #pragma unroll
                for (int nt = 0; nt < 4; nt++) {
                    MMA_BF16(acc[mt][nt], ah[mt], bh[nt]);
                    MMA_BF16(acc[mt][nt], al[mt], bh[nt]);
                    MMA_BF16(acc[mt][nt], ah[mt], bl[nt]);
                }
        }
    }

    // ------------- fused epilogue: bias + LayerNorm + GELU + split ----------
    float bcol[8], lgc[8], lbc[8];
    #pragma unroll
    for (int nt = 0; nt < 4; nt++) {
        int c = wc0 + nt * 8 + tig * 2;
        bcol[nt * 2] = __ldg(&b1[c]); bcol[nt * 2 + 1] = __ldg(&b1[c + 1]);
        lgc[nt * 2]  = __ldg(&lg[c]); lgc[nt * 2 + 1]  = __ldg(&lg[c + 1]);
        lbc[nt * 2]  = __ldg(&lb[c]); lbc[nt * 2 + 1]  = __ldg(&lb[c + 1]);
    }

    float s[8], s2[8];
    #pragma unroll
    for (int q = 0; q < 8; q++) { s[q] = 0.0f; s2[q] = 0.0f; }
    #pragma unroll
    for (int mt = 0; mt < 4; mt++)
        #pragma unroll
        for (int nt = 0; nt < 4; nt++)
            #pragma unroll
            for (int e = 0; e < 4; e++) {
                float v = acc[mt][nt][e] + bcol[nt * 2 + (e & 1)];
                acc[mt][nt][e] = v;
                int slot = mt * 2 + (e >> 1);
                s[slot] += v; s2[slot] += v * v;
            }
    #pragma unroll
    for (int q = 0; q < 8; q++) {
        s[q]  += __shfl_xor_sync(0xffffffffu, s[q],  1);
        s[q]  += __shfl_xor_sync(0xffffffffu, s[q],  2);
        s2[q] += __shfl_xor_sync(0xffffffffu, s2[q], 1);
        s2[q] += __shfl_xor_sync(0xffffffffu, s2[q], 2);
    }
    if (tig == 0) {
        #pragma unroll
        for (int mt = 0; mt < 4; mt++) {
            s_part[wid][mt * 16 + gid]     = make_float2(s[mt * 2],     s2[mt * 2]);
            s_part[wid][mt * 16 + 8 + gid] = make_float2(s[mt * 2 + 1], s2[mt * 2 + 1]);
        }
    }
    __syncthreads();
    if (tid < 64) {
        float ts = 0.0f, ts2 = 0.0f;
        #pragma unroll
        for (int w = 0; w < 8; w++) {
            float2 p = s_part[w][tid];
            ts += p.x; ts2 += p.y;
        }
        float mu   = ts * (1.0f / 256.0f);
        float var  = ts2 * (1.0f / 256.0f) - mu * mu;
        s_ln[tid] = make_float2(mu, rsqrtf(var + 1e-5f));
    }
    __syncthreads();

    #pragma unroll
    for (int mt = 0; mt < 4; mt++)
        #pragma unroll
        for (int h = 0; h < 2; h++) {
            int rl = mt * 16 + h * 8 + gid;
            float2 ln = s_ln[rl];
            int row = row0 + rl;
            #pragma unroll
            for (int nt = 0; nt < 4; nt++) {
                float v0 = acc[mt][nt][h * 2];
                float v1 = acc[mt][nt][h * 2 + 1];
                float y0 = gelu_exact((v0 - ln.x) * ln.y * lgc[nt * 2]     + lbc[nt * 2]);
                float y1 = gelu_exact((v1 - ln.x) * ln.y * lgc[nt * 2 + 1] + lbc[nt * 2 + 1]);
                uint32_t hp, lp;
                bf16_split_pack(y0, y1, hp, lp);
                int k2 = (wc0 >> 1) + nt * 4 + tig;
                g_acth[side][row][k2] = hp;
                g_actl[side][row][k2] = lp;
            }
        }
}

// ---------------------------------------------------------------------------
// GEMM2: M(B,64) = act(B,256) @ W2(256,64) + b2 -> g_m  (unchanged, passing)
// ---------------------------------------------------------------------------
__global__ __launch_bounds__(256, 2) void k_gemm2(
    const float* __restrict__ b2p, const float* __restrict__ b2v)
{
    const int side = blockIdx.y;
    const float* __restrict__ b2 = side ? b2v : b2p;

    __shared__ uint32_t Ah[128][20], Al[128][20], Bh[16][72], Bl[16][72];

    const int tid  = threadIdx.x;
    const int lane = tid & 31;
    const int wid  = tid >> 5;
    const int gid  = lane >> 2;
    const int tig  = lane & 3;
    const int wr0  = (wid & 3) * 32;
    const int wc0  = (wid >> 2) * 32;
    const int row0 = blockIdx.x * 128;

    float acc[2][4][4];
    #pragma unroll
    for (int mt = 0; mt < 2; mt++)
        #pragma unroll
        for (int nt = 0; nt < 4; nt++)
            #pragma unroll
            for (int e = 0; e < 4; e++) acc[mt][nt][e] = 0.0f;

    uint4 ahreg[2], alreg[2], bhreg, blreg;
    #pragma unroll
    for (int q = 0; q < 2; q++) {
        int idx = tid + q * 256;
        int row = idx >> 2, k2q = (idx & 3) * 4;
        ahreg[q] = *reinterpret_cast<const uint4*>(&g_acth[side][row0 + row][k2q]);
        alreg[q] = *reinterpret_cast<const uint4*>(&g_actl[side][row0 + row][k2q]);
    }
    {
        int k2l = tid >> 4, n4 = (tid & 15) * 4;
        bhreg = *reinterpret_cast<const uint4*>(&g_W2s[side][0][k2l][n4]);
        blreg = *reinterpret_cast<const uint4*>(&g_W2s[side][1][k2l][n4]);
    }

    #pragma unroll 1
    for (int kt = 0; kt < 8; kt++) {
        __syncthreads();
        #pragma unroll
        for (int q = 0; q < 2; q++) {
            int idx = tid + q * 256;
            int row = idx >> 2, k2q = (idx & 3) * 4;
            *reinterpret_cast<uint4*>(&Ah[row][k2q]) = ahreg[q];
            *reinterpret_cast<uint4*>(&Al[row][k2q]) = alreg[q];
        }
        {
            int k2l = tid >> 4, n4 = (tid & 15) * 4;
            *reinterpret_cast<uint4*>(&Bh[k2l][n4]) = bhreg;
            *reinterpret_cast<uint4*>(&Bl[k2l][n4]) = blreg;
        }
        __syncthreads();

        if (kt + 1 < 8) {
            int k2n = (kt + 1) * 16;
            #pragma unroll
            for (int q = 0; q < 2; q++) {
                int idx = tid + q * 256;
                int row = idx >> 2, k2q = (idx & 3) * 4;
                ahreg[q] = *reinterpret_cast<const uint4*>(&g_acth[side][row0 + row][k2n + k2q]);
                alreg[q] = *reinterpret_cast<const uint4*>(&g_actl[side][row0 + row][k2n + k2q]);
            }
            int k2l = tid >> 4, n4 = (tid & 15) * 4;
            bhreg = *reinterpret_cast<const uint4*>(&g_W2s[side][0][k2n + k2l][n4]);
            blreg = *reinterpret_cast<const uint4*>(&g_W2s[side][1][k2n + k2l][n4]);
        }

        #pragma unroll
        for (int k8x = 0; k8x < 16; k8x += 8) {
            uint32_t ah[2][4], al2[2][4], bh[4][2], bl[4][2];
            #pragma unroll
            for (int mt = 0; mt < 2; mt++) {
                int r = wr0 + mt * 16 + gid;
                ah[mt][0] = Ah[r][k8x + tig];     ah[mt][1] = Ah[r + 8][k8x + tig];
                ah[mt][2] = Ah[r][k8x + tig + 4]; ah[mt][3] = Ah[r + 8][k8x + tig + 4];
                al2[mt][0] = Al[r][k8x + tig];     al2[mt][1] = Al[r + 8][k8x + tig];
                al2[mt][2] = Al[r][k8x + tig + 4]; al2[mt][3] = Al[r + 8][k8x + tig + 4];
            }
            #pragma unroll
            for (int nt = 0; nt < 4; nt++) {
                int c = wc0 + nt * 8 + gid;
                bh[nt][0] = Bh[k8x + tig][c]; bh[nt][1] = Bh[k8x + tig + 4][c];
                bl[nt][0] = Bl[k8x + tig][c]; bl[nt][1] = Bl[k8x + tig + 4][c];
            }
            #pragma unroll
            for (int mt = 0; mt < 2; mt++)
                #pragma unroll
                for (int nt = 0; nt < 4; nt++) {
                    MMA_BF16(acc[mt][nt], ah[mt], bh[nt]);
                    MMA_BF16(acc[mt][nt], al2[mt], bh[nt]);
                    MMA_BF16(acc[mt][nt], ah[mt], bl[nt]);
                }
        }
    }

    #pragma unroll
    for (int mt = 0; mt < 2; mt++)
        #pragma unroll
        for (int nt = 0; nt < 4; nt++) {
            int r = row0 + wr0 + mt * 16 + gid;
            int c = wc0 + nt * 8 + tig * 2;
            float b0 = b2[c], b1b = b2[c + 1];
            float2 v0 = {acc[mt][nt][0] + b0, acc[mt][nt][1] + b1b};
            float2 v1 = {acc[mt][nt][2] + b0, acc[mt][nt][3] + b1b};
            *reinterpret_cast<float2*>(&g_m[side][r][c])     = v0;
            *reinterpret_cast<float2*>(&g_m[side][r + 8][c]) = v1;
        }
}

// ---------------------------------------------------------------------------
// VQ: Clifford collapse per row -> packed split Q.  Warp per row.
// ---------------------------------------------------------------------------
__global__ __launch_bounds__(256) void k_vq(const float* __restrict__ gw)
{
    __shared__ float s_gw[8];
    __shared__ float s_mp[8][64], s_mv[8][64], s_V[8][64], s_Q[8][64];

    const int tid = threadIdx.x;
    const int lane = tid & 31;
    const int w = tid >> 5;

    if (tid < 8) s_gw[tid] = gw[tid];
    __syncthreads();

    const int row = blockIdx.x * 8 + w;

    s_mp[w][lane]      = g_m[0][row][lane];
    s_mp[w][lane + 32] = g_m[0][row][lane + 32];
    s_mv[w][lane]      = g_m[1][row][lane];
    s_mv[w][lane + 32] = g_m[1][row][lane + 32];
    __syncwarp();

    const int MASKS_[8] = {0, 1, 2, 4, 3, 5, 6, 7};

    #pragma unroll
    for (int h = 0; h < 2; h++) {
        int f = lane + h * 32;
        int k = f >> 3, u = f & 7;
        float v = 0.0f;
        #pragma unroll
        for (int jm = 0; jm < 8; jm++) {
            int mj = MASKS_[jm];
            v += s_mv[w][k * 8 + jm] * csign(u, mj) * s_gw[cidx(u ^ mj)];
        }
        s_V[w][f] = v;
    }
    __syncwarp();

    #pragma unroll
    for (int h = 0; h < 2; h++) {
        int f = lane + h * 32;
        int k = f >> 3, jc = f & 7;
        int mjc = MASKS_[jc];
        float q = 0.0f;
        #pragma unroll
        for (int i = 0; i < 8; i++) {
            int mi = MASKS_[i];
            q += s_mp[w][k * 8 + i] * csign(mi, mjc) * s_V[w][k * 8 + (mi ^ mjc)];
        }
        s_Q[w][f] = q;
    }
    __syncwarp();

    uint32_t hp, lp;
    bf16_split_pack(s_Q[w][2 * lane], s_Q[w][2 * lane + 1], hp, lp);
    g_Qh[row][lane] = hp;
    g_Ql[row][lane] = lp;
}

// ---------------------------------------------------------------------------
// READ: out(B,95) = Q(B,64) @ T'(64,95)  (T pre-scaled 1/8), bf16 3x.
// BM=128, BN=96, BK=32. 8 warps (4m x 2n), warp tile 32x48. grid Bsz/128.
// ---------------------------------------------------------------------------
__global__ __launch_bounds__(256, 2) void k_read(float* __restrict__ out)
{
    __shared__ uint32_t Ah[128][20], Al[128][20], Bh[16][136], Bl[16][136];

    const int tid  = threadIdx.x;
    const int lane = tid & 31;
    const int wid  = tid >> 5;
    const int gid  = lane >> 2;
    const int tig  = lane & 3;
    const int wr0  = (wid & 3) * 32;
    const int wc0  = (wid >> 2) * 48;
    const int row0 = blockIdx.x * 128;

    float acc[2][6][4];
    #pragma unroll
    for (int mt = 0; mt < 2; mt++)
        #pragma unroll
        for (int nt = 0; nt < 6; nt++)
            #pragma unroll
            for (int e = 0; e < 4; e++) acc[mt][nt][e] = 0.0f;

    uint4 ahreg[2], alreg[2], bhreg[2], blreg[2];
    #pragma unroll
    for (int q = 0; q < 2; q++) {
        int idx = tid + q * 256;
        int row = idx >> 2, k2q = (idx & 3) * 4;
        ahreg[q] = *reinterpret_cast<const uint4*>(&g_Qh[row0 + row][k2q]);
        alreg[q] = *reinterpret_cast<const uint4*>(&g_Ql[row0 + row][k2q]);
        int k2l = idx >> 5, n4 = (idx & 31) * 4;
        bhreg[q] = *reinterpret_cast<const uint4*>(&g_Th[k2l][n4]);
        blreg[q] = *reinterpret_cast<const uint4*>(&g_Tl[k2l][n4]);
    }

    #pragma unroll 1
    for (int kt = 0; kt < 2; kt++) {
        __syncthreads();
        #pragma unroll
        for (int q = 0; q < 2; q++) {
            int idx = tid + q * 256;
            int row = idx >> 2, k2q = (idx & 3) * 4;
            *reinterpret_cast<uint4*>(&Ah[row][k2q]) = ahreg[q];
            *reinterpret_cast<uint4*>(&Al[row][k2q]) = alreg[q];
            int k2l = idx >> 5, n4 = (idx & 31) * 4;
            *reinterpret_cast<uint4*>(&Bh[k2l][n4]) = bhreg[q];
            *reinterpret_cast<uint4*>(&Bl[k2l][n4]) = blreg[q];
        }
        __syncthreads();

        if (kt == 0) {
            #pragma unroll
            for (int q = 0; q < 2; q++) {
                int idx = tid + q * 256;
                int row = idx >> 2, k2q = (idx & 3) * 4;
                ahreg[q] = *reinterpret_cast<const uint4*>(&g_Qh[row0 + row][16 + k2q]);
                alreg[q] = *reinterpret_cast<const uint4*>(&g_Ql[row0 + row][16 + k2q]);
                int k2l = idx >> 5, n4 = (idx & 31) * 4;
                bhreg[q] = *reinterpret_cast<const uint4*>(&g_Th[16 + k2l][n4]);
                blreg[q] = *reinterpret_cast<const uint4*>(&g_Tl[16 + k2l][n4]);
            }
        }

        #pragma unroll
        for (int k8x = 0; k8x < 16; k8x += 8) {
            uint32_t ah[2][4], al2[2][4], bh[6][2], bl[6][2];
            #pragma unroll
            for (int mt = 0; mt < 2; mt++) {
                int r = wr0 + mt * 16 + gid;
                ah[mt][0] = Ah[r][k8x + tig];     ah[mt][1] = Ah[r + 8][k8x + tig];
                ah[mt][2] = Ah[r][k8x + tig + 4]; ah[mt][3] = Ah[r + 8][k8x + tig + 4];
                al2[mt][0] = Al[r][k8x + tig];     al2[mt][1] = Al[r + 8][k8x + tig];
                al2[mt][2] = Al[r][k8x + tig + 4]; al2[mt][3] = Al[r + 8][k8x + tig + 4];
            }
            #pragma unroll
            for (int nt = 0; nt < 6; nt++) {
                int c = wc0 + nt * 8 + gid;
                bh[nt][0] = Bh[k8x + tig][c]; bh[nt][1] = Bh[k8x + tig + 4][c];
                bl[nt][0] = Bl[k8x + tig][c]; bl[nt][1] = Bl[k8x + tig + 4][c];
            }
            #pragma unroll
            for (int mt = 0; mt < 2; mt++)
                #pragma unroll
                for (int nt = 0; nt < 6; nt++) {
                    MMA_BF16(acc[mt][nt], ah[mt], bh[nt]);
                    MMA_BF16(acc[mt][nt], al2[mt], bh[nt]);
                    MMA_BF16(acc[mt][nt], ah[mt], bl[nt]);
                }
        }
    }

    #pragma unroll
    for (int mt = 0; mt < 2; mt++)
        #pragma unroll
        for (int nt = 0; nt < 6; nt++) {
            int r = row0 + wr0 + mt * 16 + gid;
            int c = wc0 + nt * 8 + tig * 2;
            if (c < Rr)     out[r * Rr + c]             = acc[mt][nt][0];
            if (c + 1 < Rr) out[r * Rr + c + 1]         = acc[mt][nt][1];
            if (c < Rr)     out[(r + 8) * Rr + c]       = acc[mt][nt][2];
            if (c + 1 < Rr) out[(r + 8) * Rr + c + 1]   = acc[mt][nt][3];
        }
}

// ---------------------------------------------------------------------------
extern "C" void kernel_launch(void* const* d_in, const int* in_sizes, int n_in,
                              void* d_out, int out_size)
{
    const float* h_perp = (const float*)d_in[0];
    const float* h_vuln = (const float*)d_in[1];
    const float* Wp1    = (const float*)d_in[2];
    const float* bp1    = (const float*)d_in[3];
    const float* lgp    = (const float*)d_in[4];
    const float* lbp    = (const float*)d_in[5];
    const float* Wp2    = (const float*)d_in[6];
    const float* bp2    = (const float*)d_in[7];
    const float* Wv1    = (const float*)d_in[8];
    const float* bv1    = (const float*)d_in[9];
    const float* lgv    = (const float*)d_in[10];
    const float* lbv    = (const float*)d_in[11];
    const float* Wv2    = (const float*)d_in[12];
    const float* bv2    = (const float*)d_in[13];
    const float* T      = (const float*)d_in[14];
    const float* gw     = (const float*)d_in[15];
    float* out = (float*)d_out;

    k_prep_w1<<<(2 * (Dd / 2) * Hh) / 256, 256>>>(Wp1, Wv1);
    k_prep_w2<<<(2 * (Hh / 2) * 64) / 256, 256>>>(Wp2, Wv2);
    k_prep_T<<<(32 * 128) / 256, 256>>>(T);
    k_gemm1f<<<dim3(Bsz / 64, 2), 256>>>(h_perp, h_vuln, bp1, bv1, lgp, lgv, lbp, lbv);
    k_gemm2<<<dim3(Bsz / 128, 2), 256>>>(bp2, bv2);
    k_vq<<<Bsz / 8, 256>>>(gw);
    k_read<<<Bsz / 128, 256>>>(out);
}

// round 11
// speedup vs baseline: 4.7337x; 1.2059x over previous
#include <cuda_runtime.h>
#include <cuda_bf16.h>
#include <stdint.h>

#define Bsz 16384
#define Dd 512
#define Hh 256
#define Rr 95

// ------------------------------- scratch -----------------------------------
__device__ uint32_t g_acth[2][Bsz][Hh / 2];   // post-GELU acts, bf16x2 hi
__device__ uint32_t g_actl[2][Bsz][Hh / 2];   // post-GELU acts, bf16x2 lo
__device__ float    g_m[2][Bsz][64];          // mp / mv multivectors
__device__ uint32_t g_W1s[2][2][Dd / 2][Hh];  // [side][hi/lo][k2][n]
__device__ uint32_t g_W2s[2][2][Hh / 2][64];
__device__ uint32_t g_Qh[Bsz][32];            // Q collapsed, bf16x2 hi (k2)
__device__ uint32_t g_Ql[Bsz][32];
__device__ uint32_t g_Th[32][128];            // T*0.125 pre-split [k2][n(pad 128)]
__device__ uint32_t g_Tl[32][128];

// ------------------------------- helpers -----------------------------------
__device__ __forceinline__ float gelu_exact(float x) {
    return 0.5f * x * (1.0f + erff(x * 0.70710678118654752440f));
}
__device__ __forceinline__ float csign(int a, int b) {
    int sw = __popc((a >> 1) & b) + __popc((a >> 2) & b);
    return (sw & 1) ? -1.0f : 1.0f;
}
__device__ __forceinline__ int cidx(int m) { return m + (m == 3) - (m == 4); }

__device__ __forceinline__ void bf16_split_pack(float x0, float x1,
                                                uint32_t& hp, uint32_t& lp) {
    __nv_bfloat16 h0 = __float2bfloat16(x0), h1 = __float2bfloat16(x1);
    float r0 = x0 - __bfloat162float(h0);
    float r1 = x1 - __bfloat162float(h1);
    __nv_bfloat16 l0 = __float2bfloat16(r0), l1 = __float2bfloat16(r1);
    hp = ((uint32_t)__bfloat16_as_ushort(h1) << 16) | (uint32_t)__bfloat16_as_ushort(h0);
    lp = ((uint32_t)__bfloat16_as_ushort(l1) << 16) | (uint32_t)__bfloat16_as_ushort(l0);
}

#define MMA_BF16(d, a, b) \
    asm volatile("mma.sync.aligned.m16n8k16.row.col.f32.bf16.bf16.f32 " \
        "{%0,%1,%2,%3}, {%4,%5,%6,%7}, {%8,%9}, {%0,%1,%2,%3};" \
        : "+f"(d[0]), "+f"(d[1]), "+f"(d[2]), "+f"(d[3]) \
        : "r"(a[0]), "r"(a[1]), "r"(a[2]), "r"(a[3]), "r"(b[0]), "r"(b[1]))

__device__ __forceinline__ void cp16(uint32_t saddr, const void* g) {
    asm volatile("cp.async.cg.shared.global [%0], [%1], 16;" :: "r"(saddr), "l"(g));
}
#define CP_COMMIT() asm volatile("cp.async.commit_group;" ::: "memory")
#define CP_WAIT0()  asm volatile("cp.async.wait_group 0;"  ::: "memory")

// ---------------------------------------------------------------------------
// prep (merged): W1 split, W2 split, T split (pre-scaled 1/8)
// ---------------------------------------------------------------------------
#define N_W1 (2 * (Dd / 2) * Hh)          // 131072 (65536 = 2^16 per side)
#define N_W2 (2 * (Hh / 2) * 64)          // 16384  (8192  = 2^13 per side)
#define N_T  (32 * 128)                   // 4096
__global__ __launch_bounds__(256) void k_prep(
    const float* __restrict__ W1p, const float* __restrict__ W1v,
    const float* __restrict__ W2p, const float* __restrict__ W2v,
    const float* __restrict__ T)
{
    int idx = blockIdx.x * 256 + threadIdx.x;
    if (idx < N_W1) {
        int side = idx >> 16;
        int rem  = idx & 0xFFFF;
        int k2   = rem >> 8;
        int n    = rem & 255;
        const float* W = side ? W1v : W1p;
        float x0 = __ldg(&W[(2 * k2) * Hh + n]);
        float x1 = __ldg(&W[(2 * k2 + 1) * Hh + n]);
        uint32_t hp, lp;
        bf16_split_pack(x0, x1, hp, lp);
        g_W1s[side][0][k2][n] = hp;
        g_W1s[side][1][k2][n] = lp;
    } else if (idx < N_W1 + N_W2) {
        int j = idx - N_W1;
        int side = j >> 13;               // FIX: 8192 = 2^13 elements per side
        int rem  = j & 0x1FFF;            // FIX
        int k2   = rem >> 6;              // 0..127
        int n    = rem & 63;
        const float* W = side ? W2v : W2p;
        float x0 = __ldg(&W[(2 * k2) * 64 + n]);
        float x1 = __ldg(&W[(2 * k2 + 1) * 64 + n]);
        uint32_t hp, lp;
        bf16_split_pack(x0, x1, hp, lp);
        g_W2s[side][0][k2][n] = hp;
        g_W2s[side][1][k2][n] = lp;
    } else if (idx < N_W1 + N_W2 + N_T) {
        int j = idx - N_W1 - N_W2;
        int k2 = j >> 7;
        int n  = j & 127;
        float x0 = 0.0f, x1 = 0.0f;
        if (n < Rr) {
            x0 = __ldg(&T[n * 64 + 2 * k2])     * 0.125f;
            x1 = __ldg(&T[n * 64 + 2 * k2 + 1]) * 0.125f;
        }
        uint32_t hp, lp;
        bf16_split_pack(x0, x1, hp, lp);
        g_Th[k2][n] = hp;
        g_Tl[k2][n] = lp;
    }
}

// ---------------------------------------------------------------------------
// GEMM1 fused + double-buffered (static smem): Y = X@W1+b1 -> LN -> GELU.
// BM=64, BN=256, BK=16 (8 k2). 8 warps (1m x 8n), warp tile 64x32.
// Stage word layout: Ah [0,576) Al [576,1152) Bh [1152,3264) Bl [3264,5376)
// 2 stages x 21504 B = 43008 B static (<48KB, no attribute needed).
// ---------------------------------------------------------------------------
#define STG_W 5376

__device__ __forceinline__ void stsA(uint32_t* __restrict__ dsm, int so,
                                     float4 a, int tid) {
    int row = tid >> 2, k2 = (tid & 3) * 2;
    uint32_t hp0, lp0, hp1, lp1;
    bf16_split_pack(a.x, a.y, hp0, lp0);
    bf16_split_pack(a.z, a.w, hp1, lp1);
    dsm[so + k2 * 72 + row]              = hp0;
    dsm[so + (k2 + 1) * 72 + row]        = hp1;
    dsm[so + 576 + k2 * 72 + row]        = lp0;
    dsm[so + 576 + (k2 + 1) * 72 + row]  = lp1;
}

__device__ __forceinline__ void cpB(uint32_t sdyn, int so, int side,
                                    int k2base, int tid) {
    #pragma unroll
    for (int q = 0; q < 2; q++) {
        int idx = tid + q * 256;
        int k2l = idx >> 6, n4 = (idx & 63) * 4;
        cp16(sdyn + (uint32_t)(so + 1152 + k2l * 264 + n4) * 4,
             &g_W1s[side][0][k2base + k2l][n4]);
        cp16(sdyn + (uint32_t)(so + 3264 + k2l * 264 + n4) * 4,
             &g_W1s[side][1][k2base + k2l][n4]);
    }
}

__global__ __launch_bounds__(256) void k_gemm1f(
    const float* __restrict__ Xp, const float* __restrict__ Xv,
    const float* __restrict__ b1p, const float* __restrict__ b1v,
    const float* __restrict__ lgp, const float* __restrict__ lgv,
    const float* __restrict__ lbp, const float* __restrict__ lbv)
{
    __shared__ uint32_t dsm[2 * STG_W];
    __shared__ float2 s_part[8][64];
    __shared__ float2 s_ln[64];

    const int side = blockIdx.y;
    const float* __restrict__ X  = side ? Xv : Xp;
    const float* __restrict__ b1 = side ? b1v : b1p;
    const float* __restrict__ lg = side ? lgv : lgp;
    const float* __restrict__ lb = side ? lbv : lbp;

    const int tid  = threadIdx.x;
    const int lane = tid & 31;
    const int wid  = tid >> 5;
    const int gid  = lane >> 2;
    const int tig  = lane & 3;
    const int wc0  = wid * 32;
    const int row0 = blockIdx.x * 64;
    const uint32_t sdyn = (uint32_t)__cvta_generic_to_shared(dsm);

    float acc[4][4][4];
    #pragma unroll
    for (int mt = 0; mt < 4; mt++)
        #pragma unroll
        for (int nt = 0; nt < 4; nt++)
            #pragma unroll
            for (int e = 0; e < 4; e++) acc[mt][nt][e] = 0.0f;

    const int arow = row0 + (tid >> 2);
    const int acol = (tid & 3) * 4;

    float4 areg;
    // ---- prologue: stage 0 ----
    areg = *reinterpret_cast<const float4*>(&X[arow * Dd + acol]);
    stsA(dsm, 0, areg, tid);
    cpB(sdyn, 0, side, 0, tid);
    CP_COMMIT();
    areg = *reinterpret_cast<const float4*>(&X[arow * Dd + 16 + acol]);
    CP_WAIT0();
    __syncthreads();

    #pragma unroll 1
    for (int kt = 0; kt < 32; kt++) {
        const int cur = (kt & 1) * STG_W;
        const int nxt = ((kt & 1) ^ 1) * STG_W;

        if (kt < 31) {
            stsA(dsm, nxt, areg, tid);               // A(kt+1) -> next stage
            cpB(sdyn, nxt, side, (kt + 1) * 8, tid);
            CP_COMMIT();
            if (kt < 30) {
                int kn = (kt + 2) * 16;
                areg = *reinterpret_cast<const float4*>(&X[arow * Dd + kn + acol]);
            }
        }

        {
            uint32_t ah[4][4], al[4][4], bh[4][2], bl[4][2];
            #pragma unroll
            for (int mt = 0; mt < 4; mt++) {
                int r = mt * 16 + gid;
                ah[mt][0] = dsm[cur + tig * 72 + r];
                ah[mt][1] = dsm[cur + tig * 72 + r + 8];
                ah[mt][2] = dsm[cur + (tig + 4) * 72 + r];
                ah[mt][3] = dsm[cur + (tig + 4) * 72 + r + 8];
                al[mt][0] = dsm[cur + 576 + tig * 72 + r];
                al[mt][1] = dsm[cur + 576 + tig * 72 + r + 8];
                al[mt][2] = dsm[cur + 576 + (tig + 4) * 72 + r];
                al[mt][3] = dsm[cur + 576 + (tig + 4) * 72 + r + 8];
            }
            #pragma unroll
            for (int nt = 0; nt < 4; nt++) {
                int c = wc0 + nt * 8 + gid;
                bh[nt][0] = dsm[cur + 1152 + tig * 264 + c];
                bh[nt][1] = dsm[cur + 1152 + (tig + 4) * 264 + c];
                bl[nt][0] = dsm[cur + 3264 + tig * 264 + c];
                bl[nt][1] = dsm[cur + 3264 + (tig + 4) * 264 + c];
            }
            #pragma unroll
            for (int mt = 0; mt < 4; mt++)
                #pragma unroll
                for (int nt = 0; nt < 4; nt++) {
                    MMA_BF16(acc[mt][nt], ah[mt], bh[nt]);
                    MMA_BF16(acc[mt][nt], al[mt], bh[nt]);
                    MMA_BF16(acc[mt][nt], ah[mt], bl[nt]);
                }
        }

        if (kt < 31) {
            CP_WAIT0();
            __syncthreads();
        }
    }

    // ------------- fused epilogue: bias + LayerNorm + GELU + split ----------
    float bcol[8], lgc[8], lbc[8];
    #pragma unroll
    for (int nt = 0; nt < 4; nt++) {
        int c = wc0 + nt * 8 + tig * 2;
        bcol[nt * 2] = __ldg(&b1[c]); bcol[nt * 2 + 1] = __ldg(&b1[c + 1]);
        lgc[nt * 2]  = __ldg(&lg[c]); lgc[nt * 2 + 1]  = __ldg(&lg[c + 1]);
        lbc[nt * 2]  = __ldg(&lb[c]); lbc[nt * 2 + 1]  = __ldg(&lb[c + 1]);
    }

    float s[8], s2[8];
    #pragma unroll
    for (int q = 0; q < 8; q++) { s[q] = 0.0f; s2[q] = 0.0f; }
    #pragma unroll
    for (int mt = 0; mt < 4; mt++)
        #pragma unroll
        for (int nt = 0; nt < 4; nt++)
            #pragma unroll
            for (int e = 0; e < 4; e++) {
                float v = acc[mt][nt][e] + bcol[nt * 2 + (e & 1)];
                acc[mt][nt][e] = v;
                int slot = mt * 2 + (e >> 1);
                s[slot] += v; s2[slot] += v * v;
            }
    #pragma unroll
    for (int q = 0; q < 8; q++) {
        s[q]  += __shfl_xor_sync(0xffffffffu, s[q],  1);
        s[q]  += __shfl_xor_sync(0xffffffffu, s[q],  2);
        s2[q] += __shfl_xor_sync(0xffffffffu, s2[q], 1);
        s2[q] += __shfl_xor_sync(0xffffffffu, s2[q], 2);
    }
    __syncthreads();
    if (tig == 0) {
        #pragma unroll
        for (int mt = 0; mt < 4; mt++) {
            s_part[wid][mt * 16 + gid]     = make_float2(s[mt * 2],     s2[mt * 2]);
            s_part[wid][mt * 16 + 8 + gid] = make_float2(s[mt * 2 + 1], s2[mt * 2 + 1]);
        }
    }
    __syncthreads();
    if (tid < 64) {
        float ts = 0.0f, ts2 = 0.0f;
        #pragma unroll
        for (int w = 0; w < 8; w++) {
            float2 p = s_part[w][tid];
            ts += p.x; ts2 += p.y;
        }
        float mu   = ts * (1.0f / 256.0f);
        float var  = ts2 * (1.0f / 256.0f) - mu * mu;
        s_ln[tid] = make_float2(mu, rsqrtf(var + 1e-5f));
    }
    __syncthreads();

    #pragma unroll
    for (int mt = 0; mt < 4; mt++)
        #pragma unroll
        for (int h = 0; h < 2; h++) {
            int rl = mt * 16 + h * 8 + gid;
            float2 ln = s_ln[rl];
            int row = row0 + rl;
            #pragma unroll
            for (int nt = 0; nt < 4; nt++) {
                float v0 = acc[mt][nt][h * 2];
                float v1 = acc[mt][nt][h * 2 + 1];
                float y0 = gelu_exact((v0 - ln.x) * ln.y * lgc[nt * 2]     + lbc[nt * 2]);
                float y1 = gelu_exact((v1 - ln.x) * ln.y * lgc[nt * 2 + 1] + lbc[nt * 2 + 1]);
                uint32_t hp, lp;
                bf16_split_pack(y0, y1, hp, lp);
                int k2 = (wc0 >> 1) + nt * 4 + tig;
                g_acth[side][row][k2] = hp;
                g_actl[side][row][k2] = lp;
            }
        }
}

// ---------------------------------------------------------------------------
// GEMM2: M(B,64) = act(B,256) @ W2(256,64) + b2 -> g_m  (unchanged, passing)
// ---------------------------------------------------------------------------
__global__ __launch_bounds__(256, 2) void k_gemm2(
    const float* __restrict__ b2p, const float* __restrict__ b2v)
{
    const int side = blockIdx.y;
    const float* __restrict__ b2 = side ? b2v : b2p;

    __shared__ uint32_t Ah[128][20], Al[128][20], Bh[16][72], Bl[16][72];

    const int tid  = threadIdx.x;
    const int lane = tid & 31;
    const int wid  = tid >> 5;
    const int gid  = lane >> 2;
    const int tig  = lane & 3;
    const int wr0  = (wid & 3) * 32;
    const int wc0  = (wid >> 2) * 32;
    const int row0 = blockIdx.x * 128;

    float acc[2][4][4];
    #pragma unroll
    for (int mt = 0; mt < 2; mt++)
        #pragma unroll
        for (int nt = 0; nt < 4; nt++)
            #pragma unroll
            for (int e = 0; e < 4; e++) acc[mt][nt][e] = 0.0f;

    uint4 ahreg[2], alreg[2], bhreg, blreg;
    #pragma unroll
    for (int q = 0; q < 2; q++) {
        int idx = tid + q * 256;
        int row = idx >> 2, k2q = (idx & 3) * 4;
        ahreg[q] = *reinterpret_cast<const uint4*>(&g_acth[side][row0 + row][k2q]);
        alreg[q] = *reinterpret_cast<const uint4*>(&g_actl[side][row0 + row][k2q]);
    }
    {
        int k2l = tid >> 4, n4 = (tid & 15) * 4;
        bhreg = *reinterpret_cast<const uint4*>(&g_W2s[side][0][k2l][n4]);
        blreg = *reinterpret_cast<const uint4*>(&g_W2s[side][1][k2l][n4]);
    }

    #pragma unroll 1
    for (int kt = 0; kt < 8; kt++) {
        __syncthreads();
        #pragma unroll
        for (int q = 0; q < 2; q++) {
            int idx = tid + q * 256;
            int row = idx >> 2, k2q = (idx & 3) * 4;
            *reinterpret_cast<uint4*>(&Ah[row][k2q]) = ahreg[q];
            *reinterpret_cast<uint4*>(&Al[row][k2q]) = alreg[q];
        }
        {
            int k2l = tid >> 4, n4 = (tid & 15) * 4;
            *reinterpret_cast<uint4*>(&Bh[k2l][n4]) = bhreg;
            *reinterpret_cast<uint4*>(&Bl[k2l][n4]) = blreg;
        }
        __syncthreads();

        if (kt + 1 < 8) {
            int k2n = (kt + 1) * 16;
            #pragma unroll
            for (int q = 0; q < 2; q++) {
                int idx = tid + q * 256;
                int row = idx >> 2, k2q = (idx & 3) * 4;
                ahreg[q] = *reinterpret_cast<const uint4*>(&g_acth[side][row0 + row][k2n + k2q]);
                alreg[q] = *reinterpret_cast<const uint4*>(&g_actl[side][row0 + row][k2n + k2q]);
            }
            int k2l = tid >> 4, n4 = (tid & 15) * 4;
            bhreg = *reinterpret_cast<const uint4*>(&g_W2s[side][0][k2n + k2l][n4]);
            blreg = *reinterpret_cast<const uint4*>(&g_W2s[side][1][k2n + k2l][n4]);
        }

        #pragma unroll
        for (int k8x = 0; k8x < 16; k8x += 8) {
            uint32_t ah[2][4], al2[2][4], bh[4][2], bl[4][2];
            #pragma unroll
            for (int mt = 0; mt < 2; mt++) {
                int r = wr0 + mt * 16 + gid;
                ah[mt][0] = Ah[r][k8x + tig];     ah[mt][1] = Ah[r + 8][k8x + tig];
                ah[mt][2] = Ah[r][k8x + tig + 4]; ah[mt][3] = Ah[r + 8][k8x + tig + 4];
                al2[mt][0] = Al[r][k8x + tig];     al2[mt][1] = Al[r + 8][k8x + tig];
                al2[mt][2] = Al[r][k8x + tig + 4]; al2[mt][3] = Al[r + 8][k8x + tig + 4];
            }
            #pragma unroll
            for (int nt = 0; nt < 4; nt++) {
                int c = wc0 + nt * 8 + gid;
                bh[nt][0] = Bh[k8x + tig][c]; bh[nt][1] = Bh[k8x + tig + 4][c];
                bl[nt][0] = Bl[k8x + tig][c]; bl[nt][1] = Bl[k8x + tig + 4][c];
            }
            #pragma unroll
            for (int mt = 0; mt < 2; mt++)
                #pragma unroll
                for (int nt = 0; nt < 4; nt++) {
                    MMA_BF16(acc[mt][nt], ah[mt], bh[nt]);
                    MMA_BF16(acc[mt][nt], al2[mt], bh[nt]);
                    MMA_BF16(acc[mt][nt], ah[mt], bl[nt]);
                }
        }
    }

    #pragma unroll
    for (int mt = 0; mt < 2; mt++)
        #pragma unroll
        for (int nt = 0; nt < 4; nt++) {
            int r = row0 + wr0 + mt * 16 + gid;
            int c = wc0 + nt * 8 + tig * 2;
            float b0 = b2[c], b1b = b2[c + 1];
            float2 v0 = {acc[mt][nt][0] + b0, acc[mt][nt][1] + b1b};
            float2 v1 = {acc[mt][nt][2] + b0, acc[mt][nt][3] + b1b};
            *reinterpret_cast<float2*>(&g_m[side][r][c])     = v0;
            *reinterpret_cast<float2*>(&g_m[side][r + 8][c]) = v1;
        }
}

// ---------------------------------------------------------------------------
// VQ: Clifford collapse per row -> packed split Q.  Warp per row.
// ---------------------------------------------------------------------------
__global__ __launch_bounds__(256) void k_vq(const float* __restrict__ gw)
{
    __shared__ float s_gw[8];
    __shared__ float s_mp[8][64], s_mv[8][64], s_V[8][64], s_Q[8][64];

    const int tid = threadIdx.x;
    const int lane = tid & 31;
    const int w = tid >> 5;

    if (tid < 8) s_gw[tid] = gw[tid];
    __syncthreads();

    const int row = blockIdx.x * 8 + w;

    s_mp[w][lane]      = g_m[0][row][lane];
    s_mp[w][lane + 32] = g_m[0][row][lane + 32];
    s_mv[w][lane]      = g_m[1][row][lane];
    s_mv[w][lane + 32] = g_m[1][row][lane + 32];
    __syncwarp();

    const int MASKS_[8] = {0, 1, 2, 4, 3, 5, 6, 7};

    #pragma unroll
    for (int h = 0; h < 2; h++) {
        int f = lane + h * 32;
        int k = f >> 3, u = f & 7;
        float v = 0.0f;
        #pragma unroll
        for (int jm = 0; jm < 8; jm++) {
            int mj = MASKS_[jm];
            v += s_mv[w][k * 8 + jm] * csign(u, mj) * s_gw[cidx(u ^ mj)];
        }
        s_V[w][f] = v;
    }
    __syncwarp();

    #pragma unroll
    for (int h = 0; h < 2; h++) {
        int f = lane + h * 32;
        int k = f >> 3, jc = f & 7;
        int mjc = MASKS_[jc];
        float q = 0.0f;
        #pragma unroll
        for (int i = 0; i < 8; i++) {
            int mi = MASKS_[i];
            q += s_mp[w][k * 8 + i] * csign(mi, mjc) * s_V[w][k * 8 + (mi ^ mjc)];
        }
        s_Q[w][f] = q;
    }
    __syncwarp();

    uint32_t hp, lp;
    bf16_split_pack(s_Q[w][2 * lane], s_Q[w][2 * lane + 1], hp, lp);
    g_Qh[row][lane] = hp;
    g_Ql[row][lane] = lp;
}

// ---------------------------------------------------------------------------
// READ: out(B,95) = Q(B,64) @ T'(64,95)  (T pre-scaled 1/8), bf16 3x.
// ---------------------------------------------------------------------------
__global__ __launch_bounds__(256, 2) void k_read(float* __restrict__ out)
{
    __shared__ uint32_t Ah[128][20], Al[128][20], Bh[16][136], Bl[16][136];

    const int tid  = threadIdx.x;
    const int lane = tid & 31;
    const int wid  = tid >> 5;
    const int gid  = lane >> 2;
    const int tig  = lane & 3;
    const int wr0  = (wid & 3) * 32;
    const int wc0  = (wid >> 2) * 48;
    const int row0 = blockIdx.x * 128;

    float acc[2][6][4];
    #pragma unroll
    for (int mt = 0; mt < 2; mt++)
        #pragma unroll
        for (int nt = 0; nt < 6; nt++)
            #pragma unroll
            for (int e = 0; e < 4; e++) acc[mt][nt][e] = 0.0f;

    uint4 ahreg[2], alreg[2], bhreg[2], blreg[2];
    #pragma unroll
    for (int q = 0; q < 2; q++) {
        int idx = tid + q * 256;
        int row = idx >> 2, k2q = (idx & 3) * 4;
        ahreg[q] = *reinterpret_cast<const uint4*>(&g_Qh[row0 + row][k2q]);
        alreg[q] = *reinterpret_cast<const uint4*>(&g_Ql[row0 + row][k2q]);
        int k2l = idx >> 5, n4 = (idx & 31) * 4;
        bhreg[q] = *reinterpret_cast<const uint4*>(&g_Th[k2l][n4]);
        blreg[q] = *reinterpret_cast<const uint4*>(&g_Tl[k2l][n4]);
    }

    #pragma unroll 1
    for (int kt = 0; kt < 2; kt++) {
        __syncthreads();
        #pragma unroll
        for (int q = 0; q < 2; q++) {
            int idx = tid + q * 256;
            int row = idx >> 2, k2q = (idx & 3) * 4;
            *reinterpret_cast<uint4*>(&Ah[row][k2q]) = ahreg[q];
            *reinterpret_cast<uint4*>(&Al[row][k2q]) = alreg[q];
            int k2l = idx >> 5, n4 = (idx & 31) * 4;
            *reinterpret_cast<uint4*>(&Bh[k2l][n4]) = bhreg[q];
            *reinterpret_cast<uint4*>(&Bl[k2l][n4]) = blreg[q];
        }
        __syncthreads();

        if (kt == 0) {
            #pragma unroll
            for (int q = 0; q < 2; q++) {
                int idx = tid + q * 256;
                int row = idx >> 2, k2q = (idx & 3) * 4;
                ahreg[q] = *reinterpret_cast<const uint4*>(&g_Qh[row0 + row][16 + k2q]);
                alreg[q] = *reinterpret_cast<const uint4*>(&g_Ql[row0 + row][16 + k2q]);
                int k2l = idx >> 5, n4 = (idx & 31) * 4;
                bhreg[q] = *reinterpret_cast<const uint4*>(&g_Th[16 + k2l][n4]);
                blreg[q] = *reinterpret_cast<const uint4*>(&g_Tl[16 + k2l][n4]);
            }
        }

        #pragma unroll
        for (int k8x = 0; k8x < 16; k8x += 8) {
            uint32_t ah[2][4], al2[2][4], bh[6][2], bl[6][2];
            #pragma unroll
            for (int mt = 0; mt < 2; mt++) {
                int r = wr0 + mt * 16 + gid;
                ah[mt][0] = Ah[r][k8x + tig];     ah[mt][1] = Ah[r + 8][k8x + tig];
                ah[mt][2] = Ah[r][k8x + tig + 4]; ah[mt][3] = Ah[r + 8][k8x + tig + 4];
                al2[mt][0] = Al[r][k8x + tig];     al2[mt][1] = Al[r + 8][k8x + tig];
                al2[mt][2] = Al[r][k8x + tig + 4]; al2[mt][3] = Al[r + 8][k8x + tig + 4];
            }
            #pragma unroll
            for (int nt = 0; nt < 6; nt++) {
                int c = wc0 + nt * 8 + gid;
                bh[nt][0] = Bh[k8x + tig][c]; bh[nt][1] = Bh[k8x + tig + 4][c];
                bl[nt][0] = Bl[k8x + tig][c]; bl[nt][1] = Bl[k8x + tig + 4][c];
            }
            #pragma unroll
            for (int mt = 0; mt < 2; mt++)
                #pragma unroll
                for (int nt = 0; nt < 6; nt++) {
                    MMA_BF16(acc[mt][nt], ah[mt], bh[nt]);
                    MMA_BF16(acc[mt][nt], al2[mt], bh[nt]);
                    MMA_BF16(acc[mt][nt], ah[mt], bl[nt]);
                }
        }
    }

    #pragma unroll
    for (int mt = 0; mt < 2; mt++)
        #pragma unroll
        for (int nt = 0; nt < 6; nt++) {
            int r = row0 + wr0 + mt * 16 + gid;
            int c = wc0 + nt * 8 + tig * 2;
            if (c < Rr)     out[r * Rr + c]             = acc[mt][nt][0];
            if (c + 1 < Rr) out[r * Rr + c + 1]         = acc[mt][nt][1];
            if (c < Rr)     out[(r + 8) * Rr + c]       = acc[mt][nt][2];
            if (c + 1 < Rr) out[(r + 8) * Rr + c + 1]   = acc[mt][nt][3];
        }
}

// ---------------------------------------------------------------------------
extern "C" void kernel_launch(void* const* d_in, const int* in_sizes, int n_in,
                              void* d_out, int out_size)
{
    const float* h_perp = (const float*)d_in[0];
    const float* h_vuln = (const float*)d_in[1];
    const float* Wp1    = (const float*)d_in[2];
    const float* bp1    = (const float*)d_in[3];
    const float* lgp    = (const float*)d_in[4];
    const float* lbp    = (const float*)d_in[5];
    const float* Wp2    = (const float*)d_in[6];
    const float* bp2    = (const float*)d_in[7];
    const float* Wv1    = (const float*)d_in[8];
    const float* bv1    = (const float*)d_in[9];
    const float* lgv    = (const float*)d_in[10];
    const float* lbv    = (const float*)d_in[11];
    const float* Wv2    = (const float*)d_in[12];
    const float* bv2    = (const float*)d_in[13];
    const float* T      = (const float*)d_in[14];
    const float* gw     = (const float*)d_in[15];
    float* out = (float*)d_out;

    k_prep<<<(N_W1 + N_W2 + N_T + 255) / 256, 256>>>(Wp1, Wv1, Wp2, Wv2, T);
    k_gemm1f<<<dim3(Bsz / 64, 2), 256>>>(h_perp, h_vuln,
        bp1, bv1, lgp, lgv, lbp, lbv);
    k_gemm2<<<dim3(Bsz / 128, 2), 256>>>(bp2, bv2);
    k_vq<<<Bsz / 8, 256>>>(gw);
    k_read<<<Bsz / 128, 256>>>(out);
}